// round 9
// baseline (speedup 1.0000x reference)
#include <cuda_runtime.h>
#include <cuda_bf16.h>
#include <math.h>
#include <stdint.h>

// ---------------- problem constants ----------------
#define B0      64
#define N0      197
#define CDIM    768
#define NHEAD   12
#define HD      64
#define FRAMES  8
#define BATCH   8            // B0 / FRAMES
#define NTOK    1576         // FRAMES * N0
#define M_G     204          // gathered tokens: 8 cls + 196
#define M_PAD   224          // padded key count (7 blocks of 32)
#define ROWS_TOT 12608       // B0 * N0 == BATCH * NTOK
#define KDIM    768

typedef unsigned long long u64;
typedef unsigned int u32;

// ---------------- scratch (device globals; no allocation allowed) ----------------
__device__ __nv_bfloat16 g_Xh[(long)ROWS_TOT * CDIM];   // x split
__device__ __nv_bfloat16 g_Xl[(long)ROWS_TOT * CDIM];
__device__ __nv_bfloat16 g_Wh[(long)3 * CDIM * KDIM];   // qkv_w split
__device__ __nv_bfloat16 g_Wl[(long)3 * CDIM * KDIM];
__device__ __nv_bfloat16 g_Ph[(long)CDIM * KDIM];       // proj_w split
__device__ __nv_bfloat16 g_Pl[(long)CDIM * KDIM];
__device__ __nv_bfloat16 g_Qh[(long)ROWS_TOT * CDIM];   // Q split (GEMM out)
__device__ __nv_bfloat16 g_Ql[(long)ROWS_TOT * CDIM];
__device__ __nv_bfloat16 g_KVh[(long)BATCH * M_G * 2 * CDIM]; // K|V split
__device__ __nv_bfloat16 g_KVl[(long)BATCH * M_G * 2 * CDIM];
__device__ __nv_bfloat16 g_Ch[(long)ROWS_TOT * CDIM];   // ctx split (attn out)
__device__ __nv_bfloat16 g_Cl[(long)ROWS_TOT * CDIM];

// ---------------- closed-form gather index / mask ----------------
__device__ __forceinline__ int idx_token(int m) {
    if (m < 8) return m * N0;
    int j = m - 8;
    int i, t;
    if (j < 100) { i = j / 25; t = j - i * 25; }
    else         { int jj = j - 100; i = 4 + jj / 24; t = jj - (i - 4) * 24; }
    return i * (N0 + 1) + 1 + 8 * t;
}
// exp coefficient: scale * maskv ; k is the (padded) key index
__device__ __forceinline__ float coef_km(int k, int fr) {
    if (k < 8) return 0.125f;
    int j = k - 8;
    int f = (j < 100) ? (j / 25) : (4 + (j - 100) / 24);
    return (f == fr) ? 0.125f : 0.1f;
}

// ---------------- warp mma helpers ----------------
__device__ __forceinline__ u32 smem_u32(const void* p) {
    u32 a;
    asm("{ .reg .u64 t; cvta.to.shared.u64 t, %1; cvt.u32.u64 %0, t; }"
        : "=r"(a) : "l"(p));
    return a;
}
__device__ __forceinline__ void ldsm4(u32* r, u32 addr) {
    asm volatile("ldmatrix.sync.aligned.m8n8.x4.shared.b16 {%0,%1,%2,%3}, [%4];"
        : "=r"(r[0]), "=r"(r[1]), "=r"(r[2]), "=r"(r[3]) : "r"(addr));
}
__device__ __forceinline__ void ldsm2(u32* r, u32 addr) {
    asm volatile("ldmatrix.sync.aligned.m8n8.x2.shared.b16 {%0,%1}, [%2];"
        : "=r"(r[0]), "=r"(r[1]) : "r"(addr));
}
__device__ __forceinline__ void ldsm2t(u32* r, u32 addr) {
    asm volatile("ldmatrix.sync.aligned.m8n8.x2.trans.shared.b16 {%0,%1}, [%2];"
        : "=r"(r[0]), "=r"(r[1]) : "r"(addr));
}
__device__ __forceinline__ void mma_bf16(float* c, const u32* a, const u32* b) {
    asm volatile("mma.sync.aligned.m16n8k16.row.col.f32.bf16.bf16.f32 "
        "{%0,%1,%2,%3}, {%4,%5,%6,%7}, {%8,%9}, {%0,%1,%2,%3};"
        : "+f"(c[0]), "+f"(c[1]), "+f"(c[2]), "+f"(c[3])
        : "r"(a[0]), "r"(a[1]), "r"(a[2]), "r"(a[3]), "r"(b[0]), "r"(b[1]));
}
__device__ __forceinline__ void split2(float x0, float x1, u32& hi, u32& lo) {
    __nv_bfloat162 h = __floats2bfloat162_rn(x0, x1);
    __nv_bfloat162 l = __floats2bfloat162_rn(x0 - __bfloat162float(h.x),
                                             x1 - __bfloat162float(h.y));
    hi = *reinterpret_cast<u32*>(&h);
    lo = *reinterpret_cast<u32*>(&l);
}

// ---------------- split kernel: fp32 -> bf16 hi + bf16 lo ----------------
__global__ void __launch_bounds__(256) split_kernel(
    const float* __restrict__ in, __nv_bfloat16* __restrict__ hi,
    __nv_bfloat16* __restrict__ lo, long n)
{
    long i = ((long)blockIdx.x * 256 + threadIdx.x) * 4;
    if (i >= n) return;
    float4 x = *(const float4*)(in + i);
    u32 h0, l0, h1, l1;
    split2(x.x, x.y, h0, l0);
    split2(x.z, x.w, h1, l1);
    *(u32*)((__nv_bfloat162*)(hi + i))     = h0;
    *(u32*)((__nv_bfloat162*)(hi + i + 2)) = h1;
    *(u32*)((__nv_bfloat162*)(lo + i))     = l0;
    *(u32*)((__nv_bfloat162*)(lo + i + 2)) = l1;
}

// ---------------- split-bf16 tensor-core GEMM ----------------
// C[M,N] = A[M,768] @ W[N,768]^T (+bias). SPLITOUT: write bf16 hi/lo instead of fp32.
#define SROW 80
#define STILE (128 * SROW)

template<bool GATHER, bool BIAS, bool SPLITOUT>
__global__ void __launch_bounds__(256) mma_gemm_kernel(
    const __nv_bfloat16* __restrict__ Ah, const __nv_bfloat16* __restrict__ Al,
    const __nv_bfloat16* __restrict__ Bh, const __nv_bfloat16* __restrict__ Bl,
    const float* __restrict__ bias, float* __restrict__ Cout,
    __nv_bfloat16* __restrict__ Oh, __nv_bfloat16* __restrict__ Ol,
    int Mrows, int Ncols)
{
    __shared__ __align__(16) char smem[4 * STILE];

    const int t = threadIdx.x;
    const int wid = t >> 5, lane = t & 31;
    const int rowTile = blockIdx.y * 128;
    const int colTile = blockIdx.x * 128;

    const int lr0 = t >> 2;
    const int seg = t & 3;
    int ar0 = rowTile + lr0;
    int ar1 = rowTile + 64 + lr0;
    if (ar0 >= Mrows) ar0 = Mrows - 1;
    if (ar1 >= Mrows) ar1 = Mrows - 1;
    if (GATHER) {
        int b0 = ar0 / M_G, m0 = ar0 - b0 * M_G;
        int b1 = ar1 / M_G, m1 = ar1 - b1 * M_G;
        ar0 = b0 * NTOK + idx_token(m0);
        ar1 = b1 * NTOK + idx_token(m1);
    }
    const long aIdx0 = (long)ar0 * KDIM + seg * 8;
    const long aIdx1 = (long)ar1 * KDIM + seg * 8;
    const long bIdx0 = (long)(colTile + lr0) * KDIM + seg * 8;
    const long bIdx1 = (long)(colTile + 64 + lr0) * KDIM + seg * 8;

    char* sAh = smem;
    char* sAl = smem + STILE;
    char* sBh = smem + 2 * STILE;
    char* sBl = smem + 3 * STILE;
    const int st0 = lr0 * SROW + seg * 16;
    const int st1 = (lr0 + 64) * SROW + seg * 16;

    const int wm = wid >> 2;
    const int wn = wid & 3;
    const u32 sb = smem_u32(smem);
    const u32 aOffH = sb             + (wm * 64 + (lane & 15)) * SROW + (lane >> 4) * 16;
    const u32 aOffL = sb + STILE     + (wm * 64 + (lane & 15)) * SROW + (lane >> 4) * 16;
    const u32 bOffH = sb + 2 * STILE + (wn * 32 + (lane & 7)) * SROW + ((lane >> 3) & 1) * 16;
    const u32 bOffL = sb + 3 * STILE + (wn * 32 + (lane & 7)) * SROW + ((lane >> 3) & 1) * 16;

    float acc[4][4][4];
#pragma unroll
    for (int i = 0; i < 4; i++)
#pragma unroll
        for (int j = 0; j < 4; j++)
#pragma unroll
            for (int q = 0; q < 4; q++) acc[i][j][q] = 0.f;

    uint4 rAh0, rAh1, rAl0, rAl1, rBh0, rBh1, rBl0, rBl1;
#define LOADC(c) do {                                                    \
    long o = (long)(c) * 32;                                             \
    rAh0 = *(const uint4*)(Ah + aIdx0 + o);                              \
    rAh1 = *(const uint4*)(Ah + aIdx1 + o);                              \
    rAl0 = *(const uint4*)(Al + aIdx0 + o);                              \
    rAl1 = *(const uint4*)(Al + aIdx1 + o);                              \
    rBh0 = *(const uint4*)(Bh + bIdx0 + o);                              \
    rBh1 = *(const uint4*)(Bh + bIdx1 + o);                              \
    rBl0 = *(const uint4*)(Bl + bIdx0 + o);                              \
    rBl1 = *(const uint4*)(Bl + bIdx1 + o);                              \
} while (0)

    LOADC(0);

    const int NCHUNK = KDIM / 32;
    for (int c = 0; c < NCHUNK; c++) {
        __syncthreads();
        *(uint4*)(sAh + st0) = rAh0;  *(uint4*)(sAh + st1) = rAh1;
        *(uint4*)(sAl + st0) = rAl0;  *(uint4*)(sAl + st1) = rAl1;
        *(uint4*)(sBh + st0) = rBh0;  *(uint4*)(sBh + st1) = rBh1;
        *(uint4*)(sBl + st0) = rBl0;  *(uint4*)(sBl + st1) = rBl1;
        if (c + 1 < NCHUNK) LOADC(c + 1);
        __syncthreads();

#pragma unroll
        for (int ks = 0; ks < 2; ks++) {
            const u32 ko = ks * 32;
            u32 bh[4][2], bl[4][2];
#pragma unroll
            for (int nf = 0; nf < 4; nf++) {
                ldsm2(bh[nf], bOffH + nf * 8 * SROW + ko);
                ldsm2(bl[nf], bOffL + nf * 8 * SROW + ko);
            }
#pragma unroll
            for (int mf = 0; mf < 4; mf++) {
                u32 ah[4], al[4];
                ldsm4(ah, aOffH + mf * 16 * SROW + ko);
                ldsm4(al, aOffL + mf * 16 * SROW + ko);
#pragma unroll
                for (int nf = 0; nf < 4; nf++) {
                    mma_bf16(acc[mf][nf], ah, bh[nf]);
                    mma_bf16(acc[mf][nf], ah, bl[nf]);
                    mma_bf16(acc[mf][nf], al, bh[nf]);
                }
            }
        }
    }
#undef LOADC

#pragma unroll
    for (int mf = 0; mf < 4; mf++) {
        const int r0 = rowTile + wm * 64 + mf * 16 + (lane >> 2);
        const int r1 = r0 + 8;
#pragma unroll
        for (int nf = 0; nf < 4; nf++) {
            const int col = colTile + wn * 32 + nf * 8 + (lane & 3) * 2;
            if (SPLITOUT) {
                if (r0 < Mrows) {
                    u32 hh, ll;
                    split2(acc[mf][nf][0], acc[mf][nf][1], hh, ll);
                    *(u32*)(Oh + (long)r0 * Ncols + col) = hh;
                    *(u32*)(Ol + (long)r0 * Ncols + col) = ll;
                }
                if (r1 < Mrows) {
                    u32 hh, ll;
                    split2(acc[mf][nf][2], acc[mf][nf][3], hh, ll);
                    *(u32*)(Oh + (long)r1 * Ncols + col) = hh;
                    *(u32*)(Ol + (long)r1 * Ncols + col) = ll;
                }
            } else {
                float b0v = 0.f, b1v = 0.f;
                if (BIAS) { b0v = bias[col]; b1v = bias[col + 1]; }
                if (r0 < Mrows) {
                    float2 v = make_float2(acc[mf][nf][0] + b0v, acc[mf][nf][1] + b1v);
                    *(float2*)(Cout + (long)r0 * Ncols + col) = v;
                }
                if (r1 < Mrows) {
                    float2 v = make_float2(acc[mf][nf][2] + b0v, acc[mf][nf][3] + b1v);
                    *(float2*)(Cout + (long)r1 * Ncols + col) = v;
                }
            }
        }
    }
}

// ---------------- tensor-core attention ----------------
// CTA = (qtile 128, head, batch). 8 warps x 16 query rows. Keys padded to 224.
// smem: Qh|Ql (128x72 bf16) + Kh|Kl|Vh|Vl (224x72 bf16), 144B row stride.
#define SROWA  144
#define QPART  (128 * SROWA)      // 18432
#define KPART  (M_PAD * SROWA)    // 32256
#define ATT_SMEM (2 * QPART + 4 * KPART)   // 165888

__global__ void __launch_bounds__(256) attn_mma_kernel(
    const __nv_bfloat16* __restrict__ Qh, const __nv_bfloat16* __restrict__ Ql,
    const __nv_bfloat16* __restrict__ KVh, const __nv_bfloat16* __restrict__ KVl,
    __nv_bfloat16* __restrict__ Ch, __nv_bfloat16* __restrict__ Cl)
{
    extern __shared__ __align__(16) char smb[];
    char* sQh = smb;
    char* sQl = smb + QPART;
    char* sKh = smb + 2 * QPART;
    char* sKl = sKh + KPART;
    char* sVh = sKl + KPART;
    char* sVl = sVh + KPART;

    const int b = blockIdx.z, h = blockIdx.y, qt = blockIdx.x;
    const int t = threadIdx.x, w = t >> 5, lane = t & 31;

    // ---- stage Q (128 rows x 8 segs of 16B per part) ----
    for (int s = t; s < 1024; s += 256) {
        int r = s >> 3, c = s & 7;
        int qrow = qt * 128 + r; if (qrow >= NTOK) qrow = NTOK - 1;
        long g = (long)(b * NTOK + qrow) * CDIM + h * HD + c * 8;
        *(uint4*)(sQh + r * SROWA + c * 16) = *(const uint4*)(Qh + g);
        *(uint4*)(sQl + r * SROWA + c * 16) = *(const uint4*)(Ql + g);
    }
    // ---- stage K/V (224 rows x 8 segs; rows >= 204 clamped, masked later) ----
    for (int s = t; s < M_PAD * 8; s += 256) {
        int m = s >> 3, c = s & 7;
        int mm = (m < M_G) ? m : (M_G - 1);
        long gk = (long)(b * M_G + mm) * (2 * CDIM) + h * HD + c * 8;
        *(uint4*)(sKh + m * SROWA + c * 16) = *(const uint4*)(KVh + gk);
        *(uint4*)(sKl + m * SROWA + c * 16) = *(const uint4*)(KVl + gk);
        *(uint4*)(sVh + m * SROWA + c * 16) = *(const uint4*)(KVh + gk + CDIM);
        *(uint4*)(sVl + m * SROWA + c * 16) = *(const uint4*)(KVl + gk + CDIM);
    }
    __syncthreads();

    // ---- Q fragments (held for whole kernel) ----
    u32 qh[4][4], ql[4][4];
    {
        u32 qaH = smem_u32(sQh) + (w * 16 + (lane & 15)) * SROWA + (lane >> 4) * 16;
        u32 qaL = smem_u32(sQl) + (w * 16 + (lane & 15)) * SROWA + (lane >> 4) * 16;
#pragma unroll
        for (int ks = 0; ks < 4; ks++) {
            ldsm4(qh[ks], qaH + ks * 32);
            ldsm4(ql[ks], qaL + ks * 32);
        }
    }

    const int q0 = qt * 128 + w * 16 + (lane >> 2);
    const int fr0 = q0 / N0;
    const int fr1 = (q0 + 8) / N0;

    float Oa[8][4];
#pragma unroll
    for (int i = 0; i < 8; i++)
#pragma unroll
        for (int j = 0; j < 4; j++) Oa[i][j] = 0.f;
    float rs0 = 0.f, rs1 = 0.f;

    const u32 kbH = smem_u32(sKh), kbL = smem_u32(sKl);
    const u32 vbH = smem_u32(sVh), vbL = smem_u32(sVl);

    for (int kb = 0; kb < M_PAD / 32; kb++) {
        float S[4][4];
#pragma unroll
        for (int i = 0; i < 4; i++)
#pragma unroll
            for (int j = 0; j < 4; j++) S[i][j] = 0.f;

#pragma unroll
        for (int ks = 0; ks < 4; ks++) {
#pragma unroll
            for (int nf = 0; nf < 4; nf++) {
                u32 kh2[2], kl2[2];
                u32 off = (u32)(kb * 32 + nf * 8 + (lane & 7)) * SROWA
                        + ((lane >> 3) & 1) * 16 + ks * 32;
                ldsm2(kh2, kbH + off);
                ldsm2(kl2, kbL + off);
                mma_bf16(S[nf], qh[ks], kh2);
                mma_bf16(S[nf], qh[ks], kl2);
                mma_bf16(S[nf], ql[ks], kh2);
            }
        }

        // ---- exp + build split P fragments in-register ----
        u32 paH[2][4], paL[2][4];
#pragma unroll
        for (int nf = 0; nf < 4; nf++) {
            int k0 = kb * 32 + nf * 8 + (lane & 3) * 2;
            int k1 = k0 + 1;
            float p00 = (k0 < M_G) ? __expf(S[nf][0] * coef_km(k0, fr0)) : 0.f;
            float p01 = (k1 < M_G) ? __expf(S[nf][1] * coef_km(k1, fr0)) : 0.f;
            float p10 = (k0 < M_G) ? __expf(S[nf][2] * coef_km(k0, fr1)) : 0.f;
            float p11 = (k1 < M_G) ? __expf(S[nf][3] * coef_km(k1, fr1)) : 0.f;
            rs0 += p00 + p01;
            rs1 += p10 + p11;
            u32 h01, l01, h23, l23;
            split2(p00, p01, h01, l01);
            split2(p10, p11, h23, l23);
            int j = nf >> 1, half = (nf & 1) << 1;
            paH[j][half]     = h01;  paL[j][half]     = l01;
            paH[j][half + 1] = h23;  paL[j][half + 1] = l23;
        }

        // ---- P @ V (ldmatrix.trans on row-major V) ----
#pragma unroll
        for (int j = 0; j < 2; j++) {
#pragma unroll
            for (int nd = 0; nd < 8; nd++) {
                u32 vh2[2], vl2[2];
                u32 off = (u32)(kb * 32 + j * 16 + (lane & 15)) * SROWA + nd * 16;
                ldsm2t(vh2, vbH + off);
                ldsm2t(vl2, vbL + off);
                mma_bf16(Oa[nd], paH[j], vh2);
                mma_bf16(Oa[nd], paH[j], vl2);
                mma_bf16(Oa[nd], paL[j], vh2);
            }
        }
    }

    // ---- row-sum reduce across quad, normalize, write split ctx ----
    rs0 += __shfl_xor_sync(0xFFFFFFFFu, rs0, 1);
    rs0 += __shfl_xor_sync(0xFFFFFFFFu, rs0, 2);
    rs1 += __shfl_xor_sync(0xFFFFFFFFu, rs1, 1);
    rs1 += __shfl_xor_sync(0xFFFFFFFFu, rs1, 2);
    const float inv0 = 1.f / rs0;
    const float inv1 = 1.f / rs1;

    const int n0 = q0;
    const int n1 = q0 + 8;
#pragma unroll
    for (int nd = 0; nd < 8; nd++) {
        int d = h * HD + nd * 8 + (lane & 3) * 2;
        if (n0 < NTOK) {
            u32 hh, ll;
            split2(Oa[nd][0] * inv0, Oa[nd][1] * inv0, hh, ll);
            long g = (long)(b * NTOK + n0) * CDIM + d;
            *(u32*)(Ch + g) = hh;
            *(u32*)(Cl + g) = ll;
        }
        if (n1 < NTOK) {
            u32 hh, ll;
            split2(Oa[nd][2] * inv1, Oa[nd][3] * inv1, hh, ll);
            long g = (long)(b * NTOK + n1) * CDIM + d;
            *(u32*)(Ch + g) = hh;
            *(u32*)(Cl + g) = ll;
        }
    }
}

// ---------------- launch ----------------
extern "C" void kernel_launch(void* const* d_in, const int* in_sizes, int n_in,
                              void* d_out, int out_size) {
    const float* x      = (const float*)d_in[0];
    const float* qkv_w  = (const float*)d_in[1];
    const float* proj_w = (const float*)d_in[2];
    const float* proj_b = (const float*)d_in[3];
    float* out          = (float*)d_out;

    __nv_bfloat16 *Xh, *Xl, *Wh, *Wl, *Ph, *Pl, *Qh, *Ql, *KVh, *KVl, *Ch, *Cl;
    cudaGetSymbolAddress((void**)&Xh,  g_Xh);
    cudaGetSymbolAddress((void**)&Xl,  g_Xl);
    cudaGetSymbolAddress((void**)&Wh,  g_Wh);
    cudaGetSymbolAddress((void**)&Wl,  g_Wl);
    cudaGetSymbolAddress((void**)&Ph,  g_Ph);
    cudaGetSymbolAddress((void**)&Pl,  g_Pl);
    cudaGetSymbolAddress((void**)&Qh,  g_Qh);
    cudaGetSymbolAddress((void**)&Ql,  g_Ql);
    cudaGetSymbolAddress((void**)&KVh, g_KVh);
    cudaGetSymbolAddress((void**)&KVl, g_KVl);
    cudaGetSymbolAddress((void**)&Ch,  g_Ch);
    cudaGetSymbolAddress((void**)&Cl,  g_Cl);

    cudaFuncSetAttribute(attn_mma_kernel,
                         cudaFuncAttributeMaxDynamicSharedMemorySize, ATT_SMEM);

    // ---- 0) split inputs ----
    {
        long nx = (long)ROWS_TOT * CDIM;
        long nw = (long)3 * CDIM * KDIM;
        long np = (long)CDIM * KDIM;
        split_kernel<<<(int)((nx / 4 + 255) / 256), 256>>>(x, Xh, Xl, nx);
        split_kernel<<<(int)((nw / 4 + 255) / 256), 256>>>(qkv_w, Wh, Wl, nw);
        split_kernel<<<(int)((np / 4 + 255) / 256), 256>>>(proj_w, Ph, Pl, np);
    }

    dim3 blk(256);

    // ---- 1) Q = X @ Wq^T  -> split bf16 ----
    {
        dim3 grid(CDIM / 128, (ROWS_TOT + 127) / 128);
        mma_gemm_kernel<false, false, true><<<grid, blk>>>(
            Xh, Xl, Wh, Wl, nullptr, nullptr, Qh, Ql, ROWS_TOT, CDIM);
    }
    // ---- 2) KV (gathered) = X[idx] @ Wkv^T -> split bf16 ----
    {
        dim3 grid((2 * CDIM) / 128, (BATCH * M_G + 127) / 128);
        mma_gemm_kernel<true, false, true><<<grid, blk>>>(
            Xh, Xl, Wh + (long)CDIM * KDIM, Wl + (long)CDIM * KDIM,
            nullptr, nullptr, KVh, KVl, BATCH * M_G, 2 * CDIM);
    }
    // ---- 3) tensor-core attention -> split bf16 ctx ----
    {
        dim3 grid((NTOK + 127) / 128, NHEAD, BATCH);   // (13, 12, 8)
        attn_mma_kernel<<<grid, 256, ATT_SMEM>>>(Qh, Ql, KVh, KVl, Ch, Cl);
    }
    // ---- 4) out = ctx @ proj_w^T + proj_b (fp32) ----
    {
        dim3 grid(CDIM / 128, (ROWS_TOT + 127) / 128);
        mma_gemm_kernel<false, true, false><<<grid, blk>>>(
            Ch, Cl, Ph, Pl, proj_b, out, nullptr, nullptr, ROWS_TOT, CDIM);
    }
}

// round 11
// speedup vs baseline: 1.5286x; 1.5286x over previous
#include <cuda_runtime.h>
#include <cuda_bf16.h>
#include <cuda_fp16.h>
#include <math.h>
#include <stdint.h>

// ---------------- problem constants ----------------
#define B0      64
#define N0      197
#define CDIM    768
#define NHEAD   12
#define HD      64
#define FRAMES  8
#define BATCH   8            // B0 / FRAMES
#define NTOK    1576         // FRAMES * N0
#define M_G     204          // gathered tokens: 8 cls + 196
#define M_PAD   224          // padded key count (7 blocks of 32)
#define ROWS_TOT 12608       // B0 * N0 == BATCH * NTOK
#define KDIM    768

typedef unsigned long long u64;
typedef unsigned int u32;

// ---------------- scratch (device globals; no allocation allowed) ----------------
__device__ float g_Q[(long)ROWS_TOT * CDIM];             // fp32 Q (GEMM out)
__device__ float g_KV[(long)BATCH * M_G * 2 * CDIM];     // fp32 K|V (GEMM out)
__device__ __nv_bfloat16 g_Xh[(long)ROWS_TOT * CDIM];    // x split
__device__ __nv_bfloat16 g_Xl[(long)ROWS_TOT * CDIM];
__device__ __nv_bfloat16 g_Wh[(long)3 * CDIM * KDIM];    // qkv_w split
__device__ __nv_bfloat16 g_Wl[(long)3 * CDIM * KDIM];
__device__ __nv_bfloat16 g_Ph[(long)CDIM * KDIM];        // proj_w split
__device__ __nv_bfloat16 g_Pl[(long)CDIM * KDIM];
__device__ __nv_bfloat16 g_Ch[(long)ROWS_TOT * CDIM];    // ctx split (attn out)
__device__ __nv_bfloat16 g_Cl[(long)ROWS_TOT * CDIM];

// ---------------- closed-form gather index ----------------
__device__ __forceinline__ int idx_token(int m) {
    if (m < 8) return m * N0;
    int j = m - 8;
    int i, t;
    if (j < 100) { i = j / 25; t = j - i * 25; }
    else         { int jj = j - 100; i = 4 + jj / 24; t = jj - (i - 4) * 24; }
    return i * (N0 + 1) + 1 + 8 * t;
}

// ---------------- warp mma helpers ----------------
__device__ __forceinline__ u32 smem_u32(const void* p) {
    u32 a;
    asm("{ .reg .u64 t; cvta.to.shared.u64 t, %1; cvt.u32.u64 %0, t; }"
        : "=r"(a) : "l"(p));
    return a;
}
__device__ __forceinline__ void ldsm4(u32* r, u32 addr) {
    asm volatile("ldmatrix.sync.aligned.m8n8.x4.shared.b16 {%0,%1,%2,%3}, [%4];"
        : "=r"(r[0]), "=r"(r[1]), "=r"(r[2]), "=r"(r[3]) : "r"(addr));
}
__device__ __forceinline__ void ldsm2(u32* r, u32 addr) {
    asm volatile("ldmatrix.sync.aligned.m8n8.x2.shared.b16 {%0,%1}, [%2];"
        : "=r"(r[0]), "=r"(r[1]) : "r"(addr));
}
__device__ __forceinline__ void ldsm2t(u32* r, u32 addr) {
    asm volatile("ldmatrix.sync.aligned.m8n8.x2.trans.shared.b16 {%0,%1}, [%2];"
        : "=r"(r[0]), "=r"(r[1]) : "r"(addr));
}
__device__ __forceinline__ void mma_bf16(float* c, const u32* a, const u32* b) {
    asm volatile("mma.sync.aligned.m16n8k16.row.col.f32.bf16.bf16.f32 "
        "{%0,%1,%2,%3}, {%4,%5,%6,%7}, {%8,%9}, {%0,%1,%2,%3};"
        : "+f"(c[0]), "+f"(c[1]), "+f"(c[2]), "+f"(c[3])
        : "r"(a[0]), "r"(a[1]), "r"(a[2]), "r"(a[3]), "r"(b[0]), "r"(b[1]));
}
__device__ __forceinline__ void mma_f16(float* c, const u32* a, const u32* b) {
    asm volatile("mma.sync.aligned.m16n8k16.row.col.f32.f16.f16.f32 "
        "{%0,%1,%2,%3}, {%4,%5,%6,%7}, {%8,%9}, {%0,%1,%2,%3};"
        : "+f"(c[0]), "+f"(c[1]), "+f"(c[2]), "+f"(c[3])
        : "r"(a[0]), "r"(a[1]), "r"(a[2]), "r"(a[3]), "r"(b[0]), "r"(b[1]));
}
__device__ __forceinline__ void split2(float x0, float x1, u32& hi, u32& lo) {
    __nv_bfloat162 h = __floats2bfloat162_rn(x0, x1);
    __nv_bfloat162 l = __floats2bfloat162_rn(x0 - __bfloat162float(h.x),
                                             x1 - __bfloat162float(h.y));
    hi = *reinterpret_cast<u32*>(&h);
    lo = *reinterpret_cast<u32*>(&l);
}
__device__ __forceinline__ u32 h2pack(float x0, float x1) {
    __half2 p = __floats2half2_rn(x0, x1);
    return *reinterpret_cast<u32*>(&p);
}

// ---------------- split kernel: fp32 -> bf16 hi + bf16 lo ----------------
__global__ void __launch_bounds__(256) split_kernel(
    const float* __restrict__ in, __nv_bfloat16* __restrict__ hi,
    __nv_bfloat16* __restrict__ lo, long n)
{
    long i = ((long)blockIdx.x * 256 + threadIdx.x) * 4;
    if (i >= n) return;
    float4 x = *(const float4*)(in + i);
    u32 h0, l0, h1, l1;
    split2(x.x, x.y, h0, l0);
    split2(x.z, x.w, h1, l1);
    *(u32*)(hi + i)     = h0;
    *(u32*)(hi + i + 2) = h1;
    *(u32*)(lo + i)     = l0;
    *(u32*)(lo + i + 2) = l1;
}

// ---------------- split-bf16 tensor-core GEMM (R4-proven, fp32 out) ----------------
#define SROW 80
#define STILE (128 * SROW)

template<bool GATHER, bool BIAS>
__global__ void __launch_bounds__(256, 2) mma_gemm_kernel(
    const __nv_bfloat16* __restrict__ Ah, const __nv_bfloat16* __restrict__ Al,
    const __nv_bfloat16* __restrict__ Bh, const __nv_bfloat16* __restrict__ Bl,
    const float* __restrict__ bias, float* __restrict__ Cout,
    int Mrows, int Ncols)
{
    __shared__ __align__(16) char smem[4 * STILE];

    const int t = threadIdx.x;
    const int wid = t >> 5, lane = t & 31;
    const int rowTile = blockIdx.y * 128;
    const int colTile = blockIdx.x * 128;

    const int lr0 = t >> 2;
    const int seg = t & 3;
    int ar0 = rowTile + lr0;
    int ar1 = rowTile + 64 + lr0;
    if (ar0 >= Mrows) ar0 = Mrows - 1;
    if (ar1 >= Mrows) ar1 = Mrows - 1;
    if (GATHER) {
        int b0 = ar0 / M_G, m0 = ar0 - b0 * M_G;
        int b1 = ar1 / M_G, m1 = ar1 - b1 * M_G;
        ar0 = b0 * NTOK + idx_token(m0);
        ar1 = b1 * NTOK + idx_token(m1);
    }
    const long aIdx0 = (long)ar0 * KDIM + seg * 8;
    const long aIdx1 = (long)ar1 * KDIM + seg * 8;
    const long bIdx0 = (long)(colTile + lr0) * KDIM + seg * 8;
    const long bIdx1 = (long)(colTile + 64 + lr0) * KDIM + seg * 8;

    char* sAh = smem;
    char* sAl = smem + STILE;
    char* sBh = smem + 2 * STILE;
    char* sBl = smem + 3 * STILE;
    const int st0 = lr0 * SROW + seg * 16;
    const int st1 = (lr0 + 64) * SROW + seg * 16;

    const int wm = wid >> 2;
    const int wn = wid & 3;
    const u32 sb = smem_u32(smem);
    const u32 aOffH = sb             + (wm * 64 + (lane & 15)) * SROW + (lane >> 4) * 16;
    const u32 aOffL = sb + STILE     + (wm * 64 + (lane & 15)) * SROW + (lane >> 4) * 16;
    const u32 bOffH = sb + 2 * STILE + (wn * 32 + (lane & 7)) * SROW + ((lane >> 3) & 1) * 16;
    const u32 bOffL = sb + 3 * STILE + (wn * 32 + (lane & 7)) * SROW + ((lane >> 3) & 1) * 16;

    float acc[4][4][4];
#pragma unroll
    for (int i = 0; i < 4; i++)
#pragma unroll
        for (int j = 0; j < 4; j++)
#pragma unroll
            for (int q = 0; q < 4; q++) acc[i][j][q] = 0.f;

    uint4 rAh0, rAh1, rAl0, rAl1, rBh0, rBh1, rBl0, rBl1;
#define LOADC(c) do {                                                    \
    long o = (long)(c) * 32;                                             \
    rAh0 = *(const uint4*)(Ah + aIdx0 + o);                              \
    rAh1 = *(const uint4*)(Ah + aIdx1 + o);                              \
    rAl0 = *(const uint4*)(Al + aIdx0 + o);                              \
    rAl1 = *(const uint4*)(Al + aIdx1 + o);                              \
    rBh0 = *(const uint4*)(Bh + bIdx0 + o);                              \
    rBh1 = *(const uint4*)(Bh + bIdx1 + o);                              \
    rBl0 = *(const uint4*)(Bl + bIdx0 + o);                              \
    rBl1 = *(const uint4*)(Bl + bIdx1 + o);                              \
} while (0)

    LOADC(0);

    const int NCHUNK = KDIM / 32;
    for (int c = 0; c < NCHUNK; c++) {
        __syncthreads();
        *(uint4*)(sAh + st0) = rAh0;  *(uint4*)(sAh + st1) = rAh1;
        *(uint4*)(sAl + st0) = rAl0;  *(uint4*)(sAl + st1) = rAl1;
        *(uint4*)(sBh + st0) = rBh0;  *(uint4*)(sBh + st1) = rBh1;
        *(uint4*)(sBl + st0) = rBl0;  *(uint4*)(sBl + st1) = rBl1;
        if (c + 1 < NCHUNK) LOADC(c + 1);
        __syncthreads();

#pragma unroll
        for (int ks = 0; ks < 2; ks++) {
            const u32 ko = ks * 32;
            u32 bh[4][2], bl[4][2];
#pragma unroll
            for (int nf = 0; nf < 4; nf++) {
                ldsm2(bh[nf], bOffH + nf * 8 * SROW + ko);
                ldsm2(bl[nf], bOffL + nf * 8 * SROW + ko);
            }
#pragma unroll
            for (int mf = 0; mf < 4; mf++) {
                u32 ah[4], al[4];
                ldsm4(ah, aOffH + mf * 16 * SROW + ko);
                ldsm4(al, aOffL + mf * 16 * SROW + ko);
#pragma unroll
                for (int nf = 0; nf < 4; nf++) {
                    mma_bf16(acc[mf][nf], ah, bh[nf]);
                    mma_bf16(acc[mf][nf], ah, bl[nf]);
                    mma_bf16(acc[mf][nf], al, bh[nf]);
                }
            }
        }
    }
#undef LOADC

#pragma unroll
    for (int mf = 0; mf < 4; mf++) {
        const int r0 = rowTile + wm * 64 + mf * 16 + (lane >> 2);
        const int r1 = r0 + 8;
#pragma unroll
        for (int nf = 0; nf < 4; nf++) {
            const int col = colTile + wn * 32 + nf * 8 + (lane & 3) * 2;
            float b0v = 0.f, b1v = 0.f;
            if (BIAS) { b0v = bias[col]; b1v = bias[col + 1]; }
            if (r0 < Mrows) {
                float2 v = make_float2(acc[mf][nf][0] + b0v, acc[mf][nf][1] + b1v);
                *(float2*)(Cout + (long)r0 * Ncols + col) = v;
            }
            if (r1 < Mrows) {
                float2 v = make_float2(acc[mf][nf][2] + b0v, acc[mf][nf][3] + b1v);
                *(float2*)(Cout + (long)r1 * Ncols + col) = v;
            }
        }
    }
}

// ---------------- tensor-core attention ----------------
// CTA = (qtile 128, head, batch). 8 warps x 16 query rows. Keys padded to 224.
// Reads fp32 Q / KV; converts during staging: Q,K -> bf16 hi/lo, V -> fp16.
// QK: 3-term split-bf16 mma. P·V: plain fp16 mma (P in [0,1], err ~2^-11).
#define SROWA  144
#define QPART  (128 * SROWA)      // 18432
#define KPART  (M_PAD * SROWA)    // 32256
#define ATT_SMEM (2 * QPART + 3 * KPART + M_PAD * 4)   // 134528

__global__ void __launch_bounds__(256) attn_mma_kernel(
    const float* __restrict__ Q, const float* __restrict__ KV,
    __nv_bfloat16* __restrict__ Ch, __nv_bfloat16* __restrict__ Cl)
{
    extern __shared__ __align__(16) char smb[];
    char* sQh = smb;
    char* sQl = smb + QPART;
    char* sKh = smb + 2 * QPART;
    char* sKl = sKh + KPART;
    char* sV  = sKl + KPART;
    int*  sKF = (int*)(sV + KPART);

    const int b = blockIdx.z, h = blockIdx.y, qt = blockIdx.x;
    const int t = threadIdx.x, w = t >> 5, lane = t & 31;

    // ---- frame table (no divisions in inner loop) ----
    if (t < M_PAD) {
        int kf = -1;
        if (t >= 8) {
            int j = t - 8;
            kf = (j < 100) ? (j / 25) : (4 + (j - 100) / 24);
        }
        sKF[t] = kf;
    }

    // ---- stage Q: 128 rows x 16 float4 segs; convert fp32 -> bf16 hi/lo ----
    for (int s = t; s < 128 * 16; s += 256) {
        int r = s >> 4, c = s & 15;
        int qrow = qt * 128 + r; if (qrow >= NTOK) qrow = NTOK - 1;
        float4 v = *(const float4*)(Q + (long)(b * NTOK + qrow) * CDIM + h * HD + c * 4);
        u32 h0, l0, h1, l1;
        split2(v.x, v.y, h0, l0);
        split2(v.z, v.w, h1, l1);
        *(uint2*)(sQh + r * SROWA + c * 8) = make_uint2(h0, h1);
        *(uint2*)(sQl + r * SROWA + c * 8) = make_uint2(l0, l1);
    }
    // ---- stage K (bf16 hi/lo) and V (fp16) ----
    for (int s = t; s < M_PAD * 16; s += 256) {
        int m = s >> 4, c = s & 15;
        int mm = (m < M_G) ? m : (M_G - 1);
        long gk = (long)(b * M_G + mm) * (2 * CDIM) + h * HD + c * 4;
        float4 kv = *(const float4*)(KV + gk);
        u32 h0, l0, h1, l1;
        split2(kv.x, kv.y, h0, l0);
        split2(kv.z, kv.w, h1, l1);
        *(uint2*)(sKh + m * SROWA + c * 8) = make_uint2(h0, h1);
        *(uint2*)(sKl + m * SROWA + c * 8) = make_uint2(l0, l1);
        float4 vv = *(const float4*)(KV + gk + CDIM);
        *(uint2*)(sV + m * SROWA + c * 8) =
            make_uint2(h2pack(vv.x, vv.y), h2pack(vv.z, vv.w));
    }
    __syncthreads();

    // ---- Q fragments (held for whole kernel) ----
    u32 qh[4][4], ql[4][4];
    {
        u32 qaH = smem_u32(sQh) + (w * 16 + (lane & 15)) * SROWA + (lane >> 4) * 16;
        u32 qaL = smem_u32(sQl) + (w * 16 + (lane & 15)) * SROWA + (lane >> 4) * 16;
#pragma unroll
        for (int ks = 0; ks < 4; ks++) {
            ldsm4(qh[ks], qaH + ks * 32);
            ldsm4(ql[ks], qaL + ks * 32);
        }
    }

    const int q0 = qt * 128 + w * 16 + (lane >> 2);
    const int fr0 = q0 / N0;
    const int fr1 = (q0 + 8) / N0;

    float Oa[8][4];
#pragma unroll
    for (int i = 0; i < 8; i++)
#pragma unroll
        for (int j = 0; j < 4; j++) Oa[i][j] = 0.f;
    float rs0 = 0.f, rs1 = 0.f;

    const u32 kbH = smem_u32(sKh), kbL = smem_u32(sKl);
    const u32 vbF = smem_u32(sV);

    for (int kb = 0; kb < M_PAD / 32; kb++) {
        float S[4][4];
#pragma unroll
        for (int i = 0; i < 4; i++)
#pragma unroll
            for (int j = 0; j < 4; j++) S[i][j] = 0.f;

#pragma unroll
        for (int ks = 0; ks < 4; ks++) {
#pragma unroll
            for (int nf = 0; nf < 4; nf++) {
                u32 kh2[2], kl2[2];
                u32 off = (u32)(kb * 32 + nf * 8 + (lane & 7)) * SROWA
                        + ((lane >> 3) & 1) * 16 + ks * 32;
                ldsm2(kh2, kbH + off);
                ldsm2(kl2, kbL + off);
                mma_bf16(S[nf], qh[ks], kh2);
                mma_bf16(S[nf], qh[ks], kl2);
                mma_bf16(S[nf], ql[ks], kh2);
            }
        }

        // ---- exp + build fp16 P fragments in-register ----
        u32 paF[2][4];
#pragma unroll
        for (int nf = 0; nf < 4; nf++) {
            int k0 = kb * 32 + nf * 8 + (lane & 3) * 2;
            int k1 = k0 + 1;
            int kf0 = sKF[k0], kf1 = sKF[k1];
            float c00 = (k0 < 8 || kf0 == fr0) ? 0.125f : 0.1f;
            float c01 = (k1 < 8 || kf1 == fr0) ? 0.125f : 0.1f;
            float c10 = (k0 < 8 || kf0 == fr1) ? 0.125f : 0.1f;
            float c11 = (k1 < 8 || kf1 == fr1) ? 0.125f : 0.1f;
            float p00 = (k0 < M_G) ? __expf(S[nf][0] * c00) : 0.f;
            float p01 = (k1 < M_G) ? __expf(S[nf][1] * c01) : 0.f;
            float p10 = (k0 < M_G) ? __expf(S[nf][2] * c10) : 0.f;
            float p11 = (k1 < M_G) ? __expf(S[nf][3] * c11) : 0.f;
            rs0 += p00 + p01;
            rs1 += p10 + p11;
            int j = nf >> 1, half = (nf & 1) << 1;
            paF[j][half]     = h2pack(p00, p01);
            paF[j][half + 1] = h2pack(p10, p11);
        }

        // ---- P @ V, fp16 single-term (ldmatrix.trans on row-major V) ----
#pragma unroll
        for (int j = 0; j < 2; j++) {
#pragma unroll
            for (int nd = 0; nd < 8; nd++) {
                u32 vf2[2];
                u32 off = (u32)(kb * 32 + j * 16 + (lane & 15)) * SROWA + nd * 16;
                ldsm2t(vf2, vbF + off);
                mma_f16(Oa[nd], paF[j], vf2);
            }
        }
    }

    // ---- row-sum reduce across quad, normalize, write split ctx ----
    rs0 += __shfl_xor_sync(0xFFFFFFFFu, rs0, 1);
    rs0 += __shfl_xor_sync(0xFFFFFFFFu, rs0, 2);
    rs1 += __shfl_xor_sync(0xFFFFFFFFu, rs1, 1);
    rs1 += __shfl_xor_sync(0xFFFFFFFFu, rs1, 2);
    const float inv0 = 1.f / rs0;
    const float inv1 = 1.f / rs1;

    const int n0 = q0;
    const int n1 = q0 + 8;
#pragma unroll
    for (int nd = 0; nd < 8; nd++) {
        int d = h * HD + nd * 8 + (lane & 3) * 2;
        if (n0 < NTOK) {
            u32 hh, ll;
            split2(Oa[nd][0] * inv0, Oa[nd][1] * inv0, hh, ll);
            long g = (long)(b * NTOK + n0) * CDIM + d;
            *(u32*)(Ch + g) = hh;
            *(u32*)(Cl + g) = ll;
        }
        if (n1 < NTOK) {
            u32 hh, ll;
            split2(Oa[nd][2] * inv1, Oa[nd][3] * inv1, hh, ll);
            long g = (long)(b * NTOK + n1) * CDIM + d;
            *(u32*)(Ch + g) = hh;
            *(u32*)(Cl + g) = ll;
        }
    }
}

// ---------------- launch ----------------
extern "C" void kernel_launch(void* const* d_in, const int* in_sizes, int n_in,
                              void* d_out, int out_size) {
    const float* x      = (const float*)d_in[0];
    const float* qkv_w  = (const float*)d_in[1];
    const float* proj_w = (const float*)d_in[2];
    const float* proj_b = (const float*)d_in[3];
    float* out          = (float*)d_out;

    float *Qp, *KVp;
    __nv_bfloat16 *Xh, *Xl, *Wh, *Wl, *Ph, *Pl, *Ch, *Cl;
    cudaGetSymbolAddress((void**)&Qp,  g_Q);
    cudaGetSymbolAddress((void**)&KVp, g_KV);
    cudaGetSymbolAddress((void**)&Xh,  g_Xh);
    cudaGetSymbolAddress((void**)&Xl,  g_Xl);
    cudaGetSymbolAddress((void**)&Wh,  g_Wh);
    cudaGetSymbolAddress((void**)&Wl,  g_Wl);
    cudaGetSymbolAddress((void**)&Ph,  g_Ph);
    cudaGetSymbolAddress((void**)&Pl,  g_Pl);
    cudaGetSymbolAddress((void**)&Ch,  g_Ch);
    cudaGetSymbolAddress((void**)&Cl,  g_Cl);

    cudaFuncSetAttribute(attn_mma_kernel,
                         cudaFuncAttributeMaxDynamicSharedMemorySize, ATT_SMEM);

    // ---- 0) split inputs ----
    {
        long nx = (long)ROWS_TOT * CDIM;
        long nw = (long)3 * CDIM * KDIM;
        long np = (long)CDIM * KDIM;
        split_kernel<<<(int)((nx / 4 + 255) / 256), 256>>>(x, Xh, Xl, nx);
        split_kernel<<<(int)((nw / 4 + 255) / 256), 256>>>(qkv_w, Wh, Wl, nw);
        split_kernel<<<(int)((np / 4 + 255) / 256), 256>>>(proj_w, Ph, Pl, np);
    }

    dim3 blk(256);

    // ---- 1) Q = X @ Wq^T  -> fp32 ----
    {
        dim3 grid(CDIM / 128, (ROWS_TOT + 127) / 128);
        mma_gemm_kernel<false, false><<<grid, blk>>>(
            Xh, Xl, Wh, Wl, nullptr, Qp, ROWS_TOT, CDIM);
    }
    // ---- 2) KV (gathered) = X[idx] @ Wkv^T -> fp32 ----
    {
        dim3 grid((2 * CDIM) / 128, (BATCH * M_G + 127) / 128);
        mma_gemm_kernel<true, false><<<grid, blk>>>(
            Xh, Xl, Wh + (long)CDIM * KDIM, Wl + (long)CDIM * KDIM,
            nullptr, KVp, BATCH * M_G, 2 * CDIM);
    }
    // ---- 3) tensor-core attention -> split bf16 ctx ----
    {
        dim3 grid((NTOK + 127) / 128, NHEAD, BATCH);   // (13, 12, 8)
        attn_mma_kernel<<<grid, 256, ATT_SMEM>>>(Qp, KVp, Ch, Cl);
    }
    // ---- 4) out = ctx @ proj_w^T + proj_b (fp32) ----
    {
        dim3 grid(CDIM / 128, (ROWS_TOT + 127) / 128);
        mma_gemm_kernel<false, true><<<grid, blk>>>(
            Ch, Cl, Ph, Pl, proj_b, out, ROWS_TOT, CDIM);
    }
}

// round 12
// speedup vs baseline: 1.7808x; 1.1650x over previous
#include <cuda_runtime.h>
#include <cuda_bf16.h>
#include <cuda_fp16.h>
#include <math.h>
#include <stdint.h>

// ---------------- problem constants ----------------
#define B0      64
#define N0      197
#define CDIM    768
#define NHEAD   12
#define HD      64
#define FRAMES  8
#define BATCH   8
#define NTOK    1576
#define M_G     204
#define M_PAD   224
#define ROWS_TOT 12608
#define KDIM    768
#define KVROWS  (BATCH * M_G)       // 1632

typedef unsigned long long u64;
typedef unsigned int u32;

// ---------------- scratch ----------------
__device__ float g_Q[(long)ROWS_TOT * CDIM];
__device__ float g_KV[(long)KVROWS * 2 * CDIM];
__device__ __nv_bfloat16 g_Xh[(long)ROWS_TOT * CDIM];
__device__ __nv_bfloat16 g_Xl[(long)ROWS_TOT * CDIM];
__device__ __nv_bfloat16 g_Wh[(long)3 * CDIM * KDIM];
__device__ __nv_bfloat16 g_Wl[(long)3 * CDIM * KDIM];
__device__ __nv_bfloat16 g_Ph[(long)CDIM * KDIM];
__device__ __nv_bfloat16 g_Pl[(long)CDIM * KDIM];
__device__ __nv_bfloat16 g_Ch[(long)ROWS_TOT * CDIM];
__device__ __nv_bfloat16 g_Cl[(long)ROWS_TOT * CDIM];

// ---------------- closed-form gather index ----------------
__device__ __forceinline__ int idx_token(int m) {
    if (m < 8) return m * N0;
    int j = m - 8;
    int i, t;
    if (j < 100) { i = j / 25; t = j - i * 25; }
    else         { int jj = j - 100; i = 4 + jj / 24; t = jj - (i - 4) * 24; }
    return i * (N0 + 1) + 1 + 8 * t;
}

// ---------------- warp mma helpers ----------------
__device__ __forceinline__ u32 smem_u32(const void* p) {
    u32 a;
    asm("{ .reg .u64 t; cvta.to.shared.u64 t, %1; cvt.u32.u64 %0, t; }"
        : "=r"(a) : "l"(p));
    return a;
}
__device__ __forceinline__ void ldsm4(u32* r, u32 addr) {
    asm volatile("ldmatrix.sync.aligned.m8n8.x4.shared.b16 {%0,%1,%2,%3}, [%4];"
        : "=r"(r[0]), "=r"(r[1]), "=r"(r[2]), "=r"(r[3]) : "r"(addr));
}
__device__ __forceinline__ void ldsm4t(u32* r, u32 addr) {
    asm volatile("ldmatrix.sync.aligned.m8n8.x4.trans.shared.b16 {%0,%1,%2,%3}, [%4];"
        : "=r"(r[0]), "=r"(r[1]), "=r"(r[2]), "=r"(r[3]) : "r"(addr));
}
__device__ __forceinline__ void mma_bf16(float* c, const u32* a, u32 b0, u32 b1) {
    asm volatile("mma.sync.aligned.m16n8k16.row.col.f32.bf16.bf16.f32 "
        "{%0,%1,%2,%3}, {%4,%5,%6,%7}, {%8,%9}, {%0,%1,%2,%3};"
        : "+f"(c[0]), "+f"(c[1]), "+f"(c[2]), "+f"(c[3])
        : "r"(a[0]), "r"(a[1]), "r"(a[2]), "r"(a[3]), "r"(b0), "r"(b1));
}
__device__ __forceinline__ void mma_f16(float* c, const u32* a, u32 b0, u32 b1) {
    asm volatile("mma.sync.aligned.m16n8k16.row.col.f32.f16.f16.f32 "
        "{%0,%1,%2,%3}, {%4,%5,%6,%7}, {%8,%9}, {%0,%1,%2,%3};"
        : "+f"(c[0]), "+f"(c[1]), "+f"(c[2]), "+f"(c[3])
        : "r"(a[0]), "r"(a[1]), "r"(a[2]), "r"(a[3]), "r"(b0), "r"(b1));
}
__device__ __forceinline__ void split2(float x0, float x1, u32& hi, u32& lo) {
    __nv_bfloat162 h = __floats2bfloat162_rn(x0, x1);
    __nv_bfloat162 l = __floats2bfloat162_rn(x0 - __bfloat162float(h.x),
                                             x1 - __bfloat162float(h.y));
    hi = *reinterpret_cast<u32*>(&h);
    lo = *reinterpret_cast<u32*>(&l);
}
__device__ __forceinline__ u32 h2pack(float x0, float x1) {
    __half2 p = __floats2half2_rn(x0, x1);
    return *reinterpret_cast<u32*>(&p);
}

// ---------------- fused split: x, qkv_w, proj_w -> bf16 hi/lo ----------------
#define NX ((long)ROWS_TOT * CDIM)
#define NW ((long)3 * CDIM * KDIM)
#define NP ((long)CDIM * KDIM)

__global__ void __launch_bounds__(256) split_all_kernel(
    const float* __restrict__ x, const float* __restrict__ w,
    const float* __restrict__ p,
    __nv_bfloat16* __restrict__ Xh, __nv_bfloat16* __restrict__ Xl,
    __nv_bfloat16* __restrict__ Wh, __nv_bfloat16* __restrict__ Wl,
    __nv_bfloat16* __restrict__ Ph, __nv_bfloat16* __restrict__ Pl)
{
    long i = ((long)blockIdx.x * 256 + threadIdx.x) * 4;
    const float* src;
    __nv_bfloat16 *hi, *lo;
    long off;
    if (i < NX)            { src = x; hi = Xh; lo = Xl; off = i; }
    else if (i < NX + NW)  { src = w; hi = Wh; lo = Wl; off = i - NX; }
    else if (i < NX + NW + NP) { src = p; hi = Ph; lo = Pl; off = i - NX - NW; }
    else return;
    float4 v = *(const float4*)(src + off);
    u32 h0, l0, h1, l1;
    split2(v.x, v.y, h0, l0);
    split2(v.z, v.w, h1, l1);
    *(u32*)(hi + off)     = h0;
    *(u32*)(hi + off + 2) = h1;
    *(u32*)(lo + off)     = l0;
    *(u32*)(lo + off + 2) = l1;
}

// ---------------- split-bf16 tensor-core GEMM, double-buffered ----------------
// MODE 0: fused QKV (750 blocks: 594 Q-part + 156 KV-part)
// MODE 1: proj (594 blocks, bias)
#define SROW 80
#define STILE (128 * SROW)            // 10240
#define GSMEM (8 * STILE)             // 81920 (2 buffers x 4 tiles)
#define QBLKS 594

template<int MODE>
__global__ void __launch_bounds__(256, 2) gemm_kernel(
    const __nv_bfloat16* __restrict__ Ah, const __nv_bfloat16* __restrict__ Al,
    const __nv_bfloat16* __restrict__ W1h, const __nv_bfloat16* __restrict__ W1l,
    const __nv_bfloat16* __restrict__ W2h, const __nv_bfloat16* __restrict__ W2l,
    const float* __restrict__ bias,
    float* __restrict__ O1, float* __restrict__ O2)
{
    extern __shared__ __align__(16) char smem[];

    const int bid = blockIdx.x;
    int rowTile, colTile, Mrows, Ncols;
    bool gather = false;
    const __nv_bfloat16 *Bh, *Bl;
    float* Out;
    if (MODE == 0) {
        if (bid < QBLKS) {
            colTile = (bid % 6) * 128;  rowTile = (bid / 6) * 128;
            Bh = W1h; Bl = W1l; Out = O1; Mrows = ROWS_TOT; Ncols = CDIM;
        } else {
            int id = bid - QBLKS;
            colTile = (id % 12) * 128;  rowTile = (id / 12) * 128;
            gather = true;
            Bh = W2h; Bl = W2l; Out = O2; Mrows = KVROWS; Ncols = 2 * CDIM;
        }
    } else {
        colTile = (bid % 6) * 128;  rowTile = (bid / 6) * 128;
        Bh = W1h; Bl = W1l; Out = O1; Mrows = ROWS_TOT; Ncols = CDIM;
    }

    const int t = threadIdx.x;
    const int wid = t >> 5, lane = t & 31;

    const int lr0 = t >> 2;
    const int seg = t & 3;
    int ar0 = rowTile + lr0;
    int ar1 = rowTile + 64 + lr0;
    if (ar0 >= Mrows) ar0 = Mrows - 1;
    if (ar1 >= Mrows) ar1 = Mrows - 1;
    if (gather) {
        int b0 = ar0 / M_G, m0 = ar0 - b0 * M_G;
        int b1 = ar1 / M_G, m1 = ar1 - b1 * M_G;
        ar0 = b0 * NTOK + idx_token(m0);
        ar1 = b1 * NTOK + idx_token(m1);
    }
    const long aIdx0 = (long)ar0 * KDIM + seg * 8;
    const long aIdx1 = (long)ar1 * KDIM + seg * 8;
    const long bIdx0 = (long)(colTile + lr0) * KDIM + seg * 8;
    const long bIdx1 = (long)(colTile + 64 + lr0) * KDIM + seg * 8;

    const int st0 = lr0 * SROW + seg * 16;
    const int st1 = st0 + 64 * SROW;

    const int wm = wid >> 2;
    const int wn = wid & 3;
    const u32 sb = smem_u32(smem);
    const u32 aRelH = (u32)((wm * 64 + (lane & 15)) * SROW + (lane >> 4) * 16);
    const u32 aRelL = aRelH + STILE;
    const u32 bRelH = (u32)(2 * STILE + (wn * 32 + (lane & 15)) * SROW + (lane >> 4) * 16);
    const u32 bRelL = bRelH + STILE;

    float acc[4][4][4];
#pragma unroll
    for (int i = 0; i < 4; i++)
#pragma unroll
        for (int j = 0; j < 4; j++)
#pragma unroll
            for (int q = 0; q < 4; q++) acc[i][j][q] = 0.f;

    uint4 rAh0, rAh1, rAl0, rAl1, rBh0, rBh1, rBl0, rBl1;
#define LOADC(c) do {                                                    \
    long o = (long)(c) * 32;                                             \
    rAh0 = *(const uint4*)(Ah + aIdx0 + o);                              \
    rAh1 = *(const uint4*)(Ah + aIdx1 + o);                              \
    rAl0 = *(const uint4*)(Al + aIdx0 + o);                              \
    rAl1 = *(const uint4*)(Al + aIdx1 + o);                              \
    rBh0 = *(const uint4*)(Bh + bIdx0 + o);                              \
    rBh1 = *(const uint4*)(Bh + bIdx1 + o);                              \
    rBl0 = *(const uint4*)(Bl + bIdx0 + o);                              \
    rBl1 = *(const uint4*)(Bl + bIdx1 + o);                              \
} while (0)

#define STSALL(base) do {                                                \
    char* _sAh = (base);                                                 \
    char* _sAl = (base) + STILE;                                         \
    char* _sBh = (base) + 2 * STILE;                                     \
    char* _sBl = (base) + 3 * STILE;                                     \
    *(uint4*)(_sAh + st0) = rAh0;  *(uint4*)(_sAh + st1) = rAh1;         \
    *(uint4*)(_sAl + st0) = rAl0;  *(uint4*)(_sAl + st1) = rAl1;         \
    *(uint4*)(_sBh + st0) = rBh0;  *(uint4*)(_sBh + st1) = rBh1;         \
    *(uint4*)(_sBl + st0) = rBl0;  *(uint4*)(_sBl + st1) = rBl1;         \
} while (0)

    LOADC(0);
    STSALL(smem);
    __syncthreads();

    const int NCHUNK = KDIM / 32;   // 24
    for (int c = 0; c < NCHUNK; c++) {
        const u32 bo = (u32)(c & 1) * (4 * STILE);
        if (c + 1 < NCHUNK) LOADC(c + 1);

#pragma unroll
        for (int ks = 0; ks < 2; ks++) {
            const u32 ko = ks * 32;
            u32 bh[4][2], bl[4][2];
#pragma unroll
            for (int nfp = 0; nfp < 2; nfp++) {
                u32 t4[4];
                ldsm4(t4, sb + bo + bRelH + nfp * 16 * SROW + ko);
                bh[2 * nfp][0] = t4[0]; bh[2 * nfp][1] = t4[2];
                bh[2 * nfp + 1][0] = t4[1]; bh[2 * nfp + 1][1] = t4[3];
                ldsm4(t4, sb + bo + bRelL + nfp * 16 * SROW + ko);
                bl[2 * nfp][0] = t4[0]; bl[2 * nfp][1] = t4[2];
                bl[2 * nfp + 1][0] = t4[1]; bl[2 * nfp + 1][1] = t4[3];
            }
#pragma unroll
            for (int mf = 0; mf < 4; mf++) {
                u32 ah[4], al[4];
                ldsm4(ah, sb + bo + aRelH + mf * 16 * SROW + ko);
                ldsm4(al, sb + bo + aRelL + mf * 16 * SROW + ko);
#pragma unroll
                for (int nf = 0; nf < 4; nf++) {
                    mma_bf16(acc[mf][nf], ah, bh[nf][0], bh[nf][1]);
                    mma_bf16(acc[mf][nf], ah, bl[nf][0], bl[nf][1]);
                    mma_bf16(acc[mf][nf], al, bh[nf][0], bh[nf][1]);
                }
            }
        }

        if (c + 1 < NCHUNK) {
            char* nb = smem + ((c + 1) & 1) * (4 * STILE);
            STSALL(nb);
            __syncthreads();
        }
    }
#undef LOADC
#undef STSALL

#pragma unroll
    for (int mf = 0; mf < 4; mf++) {
        const int r0 = rowTile + wm * 64 + mf * 16 + (lane >> 2);
        const int r1 = r0 + 8;
#pragma unroll
        for (int nf = 0; nf < 4; nf++) {
            const int col = colTile + wn * 32 + nf * 8 + (lane & 3) * 2;
            float b0v = 0.f, b1v = 0.f;
            if (MODE == 1) { b0v = bias[col]; b1v = bias[col + 1]; }
            if (r0 < Mrows) {
                float2 v = make_float2(acc[mf][nf][0] + b0v, acc[mf][nf][1] + b1v);
                *(float2*)(Out + (long)r0 * Ncols + col) = v;
            }
            if (r1 < Mrows) {
                float2 v = make_float2(acc[mf][nf][2] + b0v, acc[mf][nf][3] + b1v);
                *(float2*)(Out + (long)r1 * Ncols + col) = v;
            }
        }
    }
}

// ---------------- tensor-core attention ----------------
// smem: sQ (one part at a time, two passes) + Kh + Kl + V(fp16) + frame table.
#define SROWA  144
#define QPARTA (128 * SROWA)              // 18432
#define KPARTA (M_PAD * SROWA)            // 32256
#define ATT_SMEM (QPARTA + 3 * KPARTA + 256)   // 115456

__global__ void __launch_bounds__(256, 2) attn_mma_kernel(
    const float* __restrict__ Q, const float* __restrict__ KV,
    __nv_bfloat16* __restrict__ Ch, __nv_bfloat16* __restrict__ Cl)
{
    extern __shared__ __align__(16) char smb[];
    char* sQ  = smb;
    char* sKh = smb + QPARTA;
    char* sKl = sKh + KPARTA;
    char* sV  = sKl + KPARTA;
    char* sKF = sV + KPARTA;

    const int b = blockIdx.z, h = blockIdx.y, qt = blockIdx.x;
    const int t = threadIdx.x, w = t >> 5, lane = t & 31;

    // frame table
    if (t < M_PAD) {
        int kf = -1;
        if (t >= 8) {
            int j = t - 8;
            kf = (j < 100) ? (j / 25) : (4 + (j - 100) / 24);
        }
        sKF[t] = (char)kf;
    }

    // ---- stage K (bf16 hi/lo) and V (fp16) ----
    for (int s = t; s < M_PAD * 16; s += 256) {
        int m = s >> 4, c = s & 15;
        int mm = (m < M_G) ? m : (M_G - 1);
        long gk = (long)(b * M_G + mm) * (2 * CDIM) + h * HD + c * 4;
        float4 kv = *(const float4*)(KV + gk);
        u32 h0, l0, h1, l1;
        split2(kv.x, kv.y, h0, l0);
        split2(kv.z, kv.w, h1, l1);
        *(uint2*)(sKh + m * SROWA + c * 8) = make_uint2(h0, h1);
        *(uint2*)(sKl + m * SROWA + c * 8) = make_uint2(l0, l1);
        float4 vv = *(const float4*)(KV + gk + CDIM);
        *(uint2*)(sV + m * SROWA + c * 8) =
            make_uint2(h2pack(vv.x, vv.y), h2pack(vv.z, vv.w));
    }

    // ---- stage Q hi ----
    for (int s = t; s < 128 * 16; s += 256) {
        int r = s >> 4, c = s & 15;
        int qrow = qt * 128 + r; if (qrow >= NTOK) qrow = NTOK - 1;
        float4 v = *(const float4*)(Q + (long)(b * NTOK + qrow) * CDIM + h * HD + c * 4);
        u32 h0, l0, h1, l1;
        split2(v.x, v.y, h0, l0);
        split2(v.z, v.w, h1, l1);
        *(uint2*)(sQ + r * SROWA + c * 8) = make_uint2(h0, h1);
    }
    __syncthreads();

    u32 qh[4][4], ql[4][4];
    const u32 qa = smem_u32(sQ) + (w * 16 + (lane & 15)) * SROWA + (lane >> 4) * 16;
#pragma unroll
    for (int ks = 0; ks < 4; ks++) ldsm4(qh[ks], qa + ks * 32);
    __syncthreads();

    // ---- stage Q lo (re-read Q from L2) ----
    for (int s = t; s < 128 * 16; s += 256) {
        int r = s >> 4, c = s & 15;
        int qrow = qt * 128 + r; if (qrow >= NTOK) qrow = NTOK - 1;
        float4 v = *(const float4*)(Q + (long)(b * NTOK + qrow) * CDIM + h * HD + c * 4);
        u32 h0, l0, h1, l1;
        split2(v.x, v.y, h0, l0);
        split2(v.z, v.w, h1, l1);
        *(uint2*)(sQ + r * SROWA + c * 8) = make_uint2(l0, l1);
    }
    __syncthreads();
#pragma unroll
    for (int ks = 0; ks < 4; ks++) ldsm4(ql[ks], qa + ks * 32);

    const int q0 = qt * 128 + w * 16 + (lane >> 2);
    const int fr0 = q0 / N0;
    const int fr1 = (q0 + 8) / N0;

    float Oa[8][4];
#pragma unroll
    for (int i = 0; i < 8; i++)
#pragma unroll
        for (int j = 0; j < 4; j++) Oa[i][j] = 0.f;
    float rs0 = 0.f, rs1 = 0.f;

    const u32 kbH = smem_u32(sKh), kbL = smem_u32(sKl);
    const u32 vbF = smem_u32(sV);

    for (int kb = 0; kb < M_PAD / 32; kb++) {
        float S[4][4];
#pragma unroll
        for (int i = 0; i < 4; i++)
#pragma unroll
            for (int j = 0; j < 4; j++) S[i][j] = 0.f;

#pragma unroll
        for (int ks = 0; ks < 4; ks++) {
#pragma unroll
            for (int nfp = 0; nfp < 2; nfp++) {
                u32 off = (u32)(kb * 32 + nfp * 16 + (lane & 15)) * SROWA
                        + (lane >> 4) * 16 + ks * 32;
                u32 t4[4], s4[4];
                ldsm4(t4, kbH + off);
                ldsm4(s4, kbL + off);
                float* S0 = S[2 * nfp];
                float* S1 = S[2 * nfp + 1];
                mma_bf16(S0, qh[ks], t4[0], t4[2]);
                mma_bf16(S0, qh[ks], s4[0], s4[2]);
                mma_bf16(S0, ql[ks], t4[0], t4[2]);
                mma_bf16(S1, qh[ks], t4[1], t4[3]);
                mma_bf16(S1, qh[ks], s4[1], s4[3]);
                mma_bf16(S1, ql[ks], t4[1], t4[3]);
            }
        }

        // ---- exp + fp16 P fragments ----
        u32 paF[2][4];
#pragma unroll
        for (int nf = 0; nf < 4; nf++) {
            int k0 = kb * 32 + nf * 8 + (lane & 3) * 2;
            int k1 = k0 + 1;
            int kf0 = sKF[k0], kf1 = sKF[k1];
            float c00 = (k0 < 8 || kf0 == fr0) ? 0.125f : 0.1f;
            float c01 = (k1 < 8 || kf1 == fr0) ? 0.125f : 0.1f;
            float c10 = (k0 < 8 || kf0 == fr1) ? 0.125f : 0.1f;
            float c11 = (k1 < 8 || kf1 == fr1) ? 0.125f : 0.1f;
            float p00 = (k0 < M_G) ? __expf(S[nf][0] * c00) : 0.f;
            float p01 = (k1 < M_G) ? __expf(S[nf][1] * c01) : 0.f;
            float p10 = (k0 < M_G) ? __expf(S[nf][2] * c10) : 0.f;
            float p11 = (k1 < M_G) ? __expf(S[nf][3] * c11) : 0.f;
            rs0 += p00 + p01;
            rs1 += p10 + p11;
            int j = nf >> 1, half = (nf & 1) << 1;
            paF[j][half]     = h2pack(p00, p01);
            paF[j][half + 1] = h2pack(p10, p11);
        }

        // ---- P @ V (x4 trans ldmatrix, fp16) ----
#pragma unroll
        for (int j = 0; j < 2; j++) {
#pragma unroll
            for (int nd2 = 0; nd2 < 4; nd2++) {
                u32 v4[4];
                u32 off = (u32)(kb * 32 + j * 16 + (lane & 15)) * SROWA
                        + nd2 * 32 + (lane >> 4) * 16;
                ldsm4t(v4, vbF + off);
                mma_f16(Oa[2 * nd2],     paF[j], v4[0], v4[1]);
                mma_f16(Oa[2 * nd2 + 1], paF[j], v4[2], v4[3]);
            }
        }
    }

    // ---- reduce + normalize + write split ctx ----
    rs0 += __shfl_xor_sync(0xFFFFFFFFu, rs0, 1);
    rs0 += __shfl_xor_sync(0xFFFFFFFFu, rs0, 2);
    rs1 += __shfl_xor_sync(0xFFFFFFFFu, rs1, 1);
    rs1 += __shfl_xor_sync(0xFFFFFFFFu, rs1, 2);
    const float inv0 = 1.f / rs0;
    const float inv1 = 1.f / rs1;

    const int n0 = q0;
    const int n1 = q0 + 8;
#pragma unroll
    for (int nd = 0; nd < 8; nd++) {
        int d = h * HD + nd * 8 + (lane & 3) * 2;
        if (n0 < NTOK) {
            u32 hh, ll;
            split2(Oa[nd][0] * inv0, Oa[nd][1] * inv0, hh, ll);
            long g = (long)(b * NTOK + n0) * CDIM + d;
            *(u32*)(Ch + g) = hh;
            *(u32*)(Cl + g) = ll;
        }
        if (n1 < NTOK) {
            u32 hh, ll;
            split2(Oa[nd][2] * inv1, Oa[nd][3] * inv1, hh, ll);
            long g = (long)(b * NTOK + n1) * CDIM + d;
            *(u32*)(Ch + g) = hh;
            *(u32*)(Cl + g) = ll;
        }
    }
}

// ---------------- launch ----------------
extern "C" void kernel_launch(void* const* d_in, const int* in_sizes, int n_in,
                              void* d_out, int out_size) {
    const float* x      = (const float*)d_in[0];
    const float* qkv_w  = (const float*)d_in[1];
    const float* proj_w = (const float*)d_in[2];
    const float* proj_b = (const float*)d_in[3];
    float* out          = (float*)d_out;

    float *Qp, *KVp;
    __nv_bfloat16 *Xh, *Xl, *Wh, *Wl, *Ph, *Pl, *Ch, *Cl;
    cudaGetSymbolAddress((void**)&Qp,  g_Q);
    cudaGetSymbolAddress((void**)&KVp, g_KV);
    cudaGetSymbolAddress((void**)&Xh,  g_Xh);
    cudaGetSymbolAddress((void**)&Xl,  g_Xl);
    cudaGetSymbolAddress((void**)&Wh,  g_Wh);
    cudaGetSymbolAddress((void**)&Wl,  g_Wl);
    cudaGetSymbolAddress((void**)&Ph,  g_Ph);
    cudaGetSymbolAddress((void**)&Pl,  g_Pl);
    cudaGetSymbolAddress((void**)&Ch,  g_Ch);
    cudaGetSymbolAddress((void**)&Cl,  g_Cl);

    cudaFuncSetAttribute(gemm_kernel<0>,
                         cudaFuncAttributeMaxDynamicSharedMemorySize, GSMEM);
    cudaFuncSetAttribute(gemm_kernel<1>,
                         cudaFuncAttributeMaxDynamicSharedMemorySize, GSMEM);
    cudaFuncSetAttribute(attn_mma_kernel,
                         cudaFuncAttributeMaxDynamicSharedMemorySize, ATT_SMEM);

    // ---- 0) split all inputs (one launch) ----
    {
        long total4 = (NX + NW + NP) / 4;
        split_all_kernel<<<(int)((total4 + 255) / 256), 256>>>(
            x, qkv_w, proj_w, Xh, Xl, Wh, Wl, Ph, Pl);
    }
    // ---- 1) fused Q + KV GEMM ----
    {
        gemm_kernel<0><<<QBLKS + 156, 256, GSMEM>>>(
            Xh, Xl, Wh, Wl,
            Wh + (long)CDIM * KDIM, Wl + (long)CDIM * KDIM,
            nullptr, Qp, KVp);
    }
    // ---- 2) tensor-core attention -> split bf16 ctx ----
    {
        dim3 grid((NTOK + 127) / 128, NHEAD, BATCH);
        attn_mma_kernel<<<grid, 256, ATT_SMEM>>>(Qp, KVp, Ch, Cl);
    }
    // ---- 3) out = ctx @ proj_w^T + proj_b ----
    {
        gemm_kernel<1><<<QBLKS, 256, GSMEM>>>(
            Ch, Cl, Ph, Pl, nullptr, nullptr, proj_b, out, nullptr);
    }
}

// round 13
// speedup vs baseline: 1.9306x; 1.0841x over previous
#include <cuda_runtime.h>
#include <cuda_bf16.h>
#include <cuda_fp16.h>
#include <math.h>
#include <stdint.h>

// ---------------- problem constants ----------------
#define B0      64
#define N0      197
#define CDIM    768
#define NHEAD   12
#define HD      64
#define FRAMES  8
#define BATCH   8
#define NTOK    1576
#define M_G     204
#define M_PAD   224
#define ROWS_TOT 12608
#define KDIM    768
#define KVROWS  (BATCH * M_G)       // 1632

typedef unsigned long long u64;
typedef unsigned int u32;

// ---------------- scratch ----------------
__device__ float g_Q[(long)ROWS_TOT * CDIM];
__device__ float g_KV[(long)KVROWS * 2 * CDIM];
__device__ __nv_bfloat16 g_Ph[(long)CDIM * KDIM];
__device__ __nv_bfloat16 g_Pl[(long)CDIM * KDIM];
__device__ __nv_bfloat16 g_Ch[(long)ROWS_TOT * CDIM];
__device__ __nv_bfloat16 g_Cl[(long)ROWS_TOT * CDIM];

// ---------------- closed-form gather index ----------------
__device__ __forceinline__ int idx_token(int m) {
    if (m < 8) return m * N0;
    int j = m - 8;
    int i, t;
    if (j < 100) { i = j / 25; t = j - i * 25; }
    else         { int jj = j - 100; i = 4 + jj / 24; t = jj - (i - 4) * 24; }
    return i * (N0 + 1) + 1 + 8 * t;
}

// ---------------- helpers ----------------
__device__ __forceinline__ u32 smem_u32(const void* p) {
    u32 a;
    asm("{ .reg .u64 t; cvta.to.shared.u64 t, %1; cvt.u32.u64 %0, t; }"
        : "=r"(a) : "l"(p));
    return a;
}
__device__ __forceinline__ void ldsm4(u32* r, u32 addr) {
    asm volatile("ldmatrix.sync.aligned.m8n8.x4.shared.b16 {%0,%1,%2,%3}, [%4];"
        : "=r"(r[0]), "=r"(r[1]), "=r"(r[2]), "=r"(r[3]) : "r"(addr));
}
__device__ __forceinline__ void ldsm4t(u32* r, u32 addr) {
    asm volatile("ldmatrix.sync.aligned.m8n8.x4.trans.shared.b16 {%0,%1,%2,%3}, [%4];"
        : "=r"(r[0]), "=r"(r[1]), "=r"(r[2]), "=r"(r[3]) : "r"(addr));
}
__device__ __forceinline__ void mma_bf16(float* c, const u32* a, u32 b0, u32 b1) {
    asm volatile("mma.sync.aligned.m16n8k16.row.col.f32.bf16.bf16.f32 "
        "{%0,%1,%2,%3}, {%4,%5,%6,%7}, {%8,%9}, {%0,%1,%2,%3};"
        : "+f"(c[0]), "+f"(c[1]), "+f"(c[2]), "+f"(c[3])
        : "r"(a[0]), "r"(a[1]), "r"(a[2]), "r"(a[3]), "r"(b0), "r"(b1));
}
__device__ __forceinline__ void mma_f16(float* c, const u32* a, u32 b0, u32 b1) {
    asm volatile("mma.sync.aligned.m16n8k16.row.col.f32.f16.f16.f32 "
        "{%0,%1,%2,%3}, {%4,%5,%6,%7}, {%8,%9}, {%0,%1,%2,%3};"
        : "+f"(c[0]), "+f"(c[1]), "+f"(c[2]), "+f"(c[3])
        : "r"(a[0]), "r"(a[1]), "r"(a[2]), "r"(a[3]), "r"(b0), "r"(b1));
}
__device__ __forceinline__ void mma_tf32(float* c, float a0, float a1, float a2, float a3,
                                         float b0, float b1) {
    asm volatile("mma.sync.aligned.m16n8k8.row.col.f32.tf32.tf32.f32 "
        "{%0,%1,%2,%3}, {%4,%5,%6,%7}, {%8,%9}, {%0,%1,%2,%3};"
        : "+f"(c[0]), "+f"(c[1]), "+f"(c[2]), "+f"(c[3])
        : "r"(__float_as_uint(a0)), "r"(__float_as_uint(a1)),
          "r"(__float_as_uint(a2)), "r"(__float_as_uint(a3)),
          "r"(__float_as_uint(b0)), "r"(__float_as_uint(b1)));
}
__device__ __forceinline__ float cvt_tf32(float x) {
    u32 r;
    asm("cvt.rna.tf32.f32 %0, %1;" : "=r"(r) : "f"(x));
    return __uint_as_float(r);
}
__device__ __forceinline__ void split2(float x0, float x1, u32& hi, u32& lo) {
    __nv_bfloat162 h = __floats2bfloat162_rn(x0, x1);
    __nv_bfloat162 l = __floats2bfloat162_rn(x0 - __bfloat162float(h.x),
                                             x1 - __bfloat162float(h.y));
    hi = *reinterpret_cast<u32*>(&h);
    lo = *reinterpret_cast<u32*>(&l);
}
__device__ __forceinline__ u32 h2pack(float x0, float x1) {
    __half2 p = __floats2half2_rn(x0, x1);
    return *reinterpret_cast<u32*>(&p);
}

// ---------------- split kernel (proj weights only) ----------------
__global__ void __launch_bounds__(256) split_kernel(
    const float* __restrict__ in, __nv_bfloat16* __restrict__ hi,
    __nv_bfloat16* __restrict__ lo, long n)
{
    long i = ((long)blockIdx.x * 256 + threadIdx.x) * 4;
    if (i >= n) return;
    float4 x = *(const float4*)(in + i);
    u32 h0, l0, h1, l1;
    split2(x.x, x.y, h0, l0);
    split2(x.z, x.w, h1, l1);
    *(u32*)(hi + i)     = h0;
    *(u32*)(hi + i + 2) = h1;
    *(u32*)(lo + i)     = l0;
    *(u32*)(lo + i + 2) = l1;
}

// ---------------- tf32 fused QKV GEMM ----------------
// Q part: 594 blocks (12608x768); KV part: 156 blocks (1632x1536, gathered A rows).
// Tile 128x128, chunk 32, double-buffered fp32 smem (tf32-rounded), 1-term k8 MMA.
#define FROW 36                      // floats per smem row (144 B)
#define FTILE (128 * FROW)           // floats per tile
#define QKV_SMEM (2 * 2 * FTILE * 4) // 73728 B
#define QBLKS 594

__global__ void __launch_bounds__(256, 2) qkv_tf32_kernel(
    const float* __restrict__ X, const float* __restrict__ Wq,
    const float* __restrict__ Wkv,
    float* __restrict__ Qout, float* __restrict__ KVout)
{
    extern __shared__ __align__(16) float fs[];

    const int bid = blockIdx.x;
    int rowTile, colTile, Mrows, Ncols;
    bool gather;
    const float* W;
    float* Out;
    if (bid < QBLKS) {
        colTile = (bid % 6) * 128;  rowTile = (bid / 6) * 128;
        gather = false; W = Wq; Out = Qout; Mrows = ROWS_TOT; Ncols = CDIM;
    } else {
        int id = bid - QBLKS;
        colTile = (id % 12) * 128;  rowTile = (id / 12) * 128;
        gather = true; W = Wkv; Out = KVout; Mrows = KVROWS; Ncols = 2 * CDIM;
    }

    const int t = threadIdx.x;
    const int wid = t >> 5, lane = t & 31;
    const int wm = wid >> 2, wn = wid & 3;

    // global load mapping: thread -> one row, 16-float half
    const int lrow = t >> 1;          // 0..127
    const int half = t & 1;
    int arow = rowTile + lrow;
    if (arow >= Mrows) arow = Mrows - 1;
    if (gather) {
        int b = arow / M_G, m = arow - b * M_G;
        arow = b * NTOK + idx_token(m);
    }
    const long aIdx = (long)arow * KDIM + half * 16;
    const long bIdx = (long)(colTile + lrow) * KDIM + half * 16;
    const int stw = lrow * FROW + half * 16;   // word offset in tile

    float rA[16], rB[16];
#define LOADC(c) do {                                                  \
    long o = (long)(c) * 32;                                           \
    *(float4*)(rA + 0)  = *(const float4*)(X + aIdx + o);              \
    *(float4*)(rA + 4)  = *(const float4*)(X + aIdx + o + 4);          \
    *(float4*)(rA + 8)  = *(const float4*)(X + aIdx + o + 8);          \
    *(float4*)(rA + 12) = *(const float4*)(X + aIdx + o + 12);         \
    *(float4*)(rB + 0)  = *(const float4*)(W + bIdx + o);              \
    *(float4*)(rB + 4)  = *(const float4*)(W + bIdx + o + 4);          \
    *(float4*)(rB + 8)  = *(const float4*)(W + bIdx + o + 8);          \
    *(float4*)(rB + 12) = *(const float4*)(W + bIdx + o + 12);         \
} while (0)

#define STSALL(boff) do {                                              \
    float* _a = fs + (boff);                                           \
    float* _b = fs + (boff) + FTILE;                                   \
    _Pragma("unroll")                                                  \
    for (int i = 0; i < 16; i += 4) {                                  \
        float4 va = make_float4(cvt_tf32(rA[i]), cvt_tf32(rA[i+1]),    \
                                cvt_tf32(rA[i+2]), cvt_tf32(rA[i+3])); \
        float4 vb = make_float4(cvt_tf32(rB[i]), cvt_tf32(rB[i+1]),    \
                                cvt_tf32(rB[i+2]), cvt_tf32(rB[i+3])); \
        *(float4*)(_a + stw + i) = va;                                 \
        *(float4*)(_b + stw + i) = vb;                                 \
    }                                                                  \
} while (0)

    float acc[4][4][4];
#pragma unroll
    for (int i = 0; i < 4; i++)
#pragma unroll
        for (int j = 0; j < 4; j++)
#pragma unroll
            for (int q = 0; q < 4; q++) acc[i][j][q] = 0.f;

    LOADC(0);
    STSALL(0);
    __syncthreads();

    const int rA0 = wm * 64 + (lane >> 2);   // A frag base row
    const int nB0 = wn * 32 + (lane >> 2);   // B frag base row (per nf +8)
    const int kc  = lane & 3;

    const int NCHUNK = KDIM / 32;   // 24
    for (int c = 0; c < NCHUNK; c++) {
        const int bo = (c & 1) * (2 * FTILE);
        if (c + 1 < NCHUNK) LOADC(c + 1);

        const float* As = fs + bo;
        const float* Bs = fs + bo + FTILE;

#pragma unroll
        for (int ks = 0; ks < 4; ks++) {
            const int k = ks * 8 + kc;
            float b0[4], b1[4];
#pragma unroll
            for (int nf = 0; nf < 4; nf++) {
                const float* br = Bs + (nB0 + nf * 8) * FROW;
                b0[nf] = br[k];
                b1[nf] = br[k + 4];
            }
#pragma unroll
            for (int mf = 0; mf < 4; mf++) {
                const float* ar0 = As + (rA0 + mf * 16) * FROW;
                const float* ar1 = ar0 + 8 * FROW;
                float a0 = ar0[k], a1 = ar1[k], a2 = ar0[k + 4], a3 = ar1[k + 4];
#pragma unroll
                for (int nf = 0; nf < 4; nf++)
                    mma_tf32(acc[mf][nf], a0, a1, a2, a3, b0[nf], b1[nf]);
            }
        }

        if (c + 1 < NCHUNK) {
            STSALL(((c + 1) & 1) * (2 * FTILE));
            __syncthreads();
        }
    }
#undef LOADC
#undef STSALL

#pragma unroll
    for (int mf = 0; mf < 4; mf++) {
        const int r0 = rowTile + wm * 64 + mf * 16 + (lane >> 2);
        const int r1 = r0 + 8;
#pragma unroll
        for (int nf = 0; nf < 4; nf++) {
            const int col = colTile + wn * 32 + nf * 8 + (lane & 3) * 2;
            if (r0 < Mrows)
                *(float2*)(Out + (long)r0 * Ncols + col) =
                    make_float2(acc[mf][nf][0], acc[mf][nf][1]);
            if (r1 < Mrows)
                *(float2*)(Out + (long)r1 * Ncols + col) =
                    make_float2(acc[mf][nf][2], acc[mf][nf][3]);
        }
    }
}

// ---------------- proj GEMM: split-bf16 3-term (proven) ----------------
#define SROW 80
#define STILE (128 * SROW)
#define GSMEM (8 * STILE)

__global__ void __launch_bounds__(256, 2) proj_gemm_kernel(
    const __nv_bfloat16* __restrict__ Ah, const __nv_bfloat16* __restrict__ Al,
    const __nv_bfloat16* __restrict__ Bh, const __nv_bfloat16* __restrict__ Bl,
    const float* __restrict__ bias, float* __restrict__ Out)
{
    extern __shared__ __align__(16) char smem[];

    const int bid = blockIdx.x;
    const int colTile = (bid % 6) * 128;
    const int rowTile = (bid / 6) * 128;
    const int Mrows = ROWS_TOT, Ncols = CDIM;

    const int t = threadIdx.x;
    const int wid = t >> 5, lane = t & 31;

    const int lr0 = t >> 2;
    const int seg = t & 3;
    int ar0 = rowTile + lr0;
    int ar1 = rowTile + 64 + lr0;
    if (ar0 >= Mrows) ar0 = Mrows - 1;
    if (ar1 >= Mrows) ar1 = Mrows - 1;
    const long aIdx0 = (long)ar0 * KDIM + seg * 8;
    const long aIdx1 = (long)ar1 * KDIM + seg * 8;
    const long bIdx0 = (long)(colTile + lr0) * KDIM + seg * 8;
    const long bIdx1 = (long)(colTile + 64 + lr0) * KDIM + seg * 8;

    const int st0 = lr0 * SROW + seg * 16;
    const int st1 = st0 + 64 * SROW;

    const int wm = wid >> 2;
    const int wn = wid & 3;
    const u32 sb = smem_u32(smem);
    const u32 aRelH = (u32)((wm * 64 + (lane & 15)) * SROW + (lane >> 4) * 16);
    const u32 aRelL = aRelH + STILE;
    const u32 bRelH = (u32)(2 * STILE + (wn * 32 + (lane & 15)) * SROW + (lane >> 4) * 16);
    const u32 bRelL = bRelH + STILE;

    float acc[4][4][4];
#pragma unroll
    for (int i = 0; i < 4; i++)
#pragma unroll
        for (int j = 0; j < 4; j++)
#pragma unroll
            for (int q = 0; q < 4; q++) acc[i][j][q] = 0.f;

    uint4 rAh0, rAh1, rAl0, rAl1, rBh0, rBh1, rBl0, rBl1;
#define LOADC(c) do {                                                    \
    long o = (long)(c) * 32;                                             \
    rAh0 = *(const uint4*)(Ah + aIdx0 + o);                              \
    rAh1 = *(const uint4*)(Ah + aIdx1 + o);                              \
    rAl0 = *(const uint4*)(Al + aIdx0 + o);                              \
    rAl1 = *(const uint4*)(Al + aIdx1 + o);                              \
    rBh0 = *(const uint4*)(Bh + bIdx0 + o);                              \
    rBh1 = *(const uint4*)(Bh + bIdx1 + o);                              \
    rBl0 = *(const uint4*)(Bl + bIdx0 + o);                              \
    rBl1 = *(const uint4*)(Bl + bIdx1 + o);                              \
} while (0)

#define STSALL(base) do {                                                \
    char* _sAh = (base);                                                 \
    char* _sAl = (base) + STILE;                                         \
    char* _sBh = (base) + 2 * STILE;                                     \
    char* _sBl = (base) + 3 * STILE;                                     \
    *(uint4*)(_sAh + st0) = rAh0;  *(uint4*)(_sAh + st1) = rAh1;         \
    *(uint4*)(_sAl + st0) = rAl0;  *(uint4*)(_sAl + st1) = rAl1;         \
    *(uint4*)(_sBh + st0) = rBh0;  *(uint4*)(_sBh + st1) = rBh1;         \
    *(uint4*)(_sBl + st0) = rBl0;  *(uint4*)(_sBl + st1) = rBl1;         \
} while (0)

    LOADC(0);
    STSALL(smem);
    __syncthreads();

    const int NCHUNK = KDIM / 32;
    for (int c = 0; c < NCHUNK; c++) {
        const u32 bo = (u32)(c & 1) * (4 * STILE);
        if (c + 1 < NCHUNK) LOADC(c + 1);

#pragma unroll
        for (int ks = 0; ks < 2; ks++) {
            const u32 ko = ks * 32;
            u32 bh[4][2], bl[4][2];
#pragma unroll
            for (int nfp = 0; nfp < 2; nfp++) {
                u32 t4[4];
                ldsm4(t4, sb + bo + bRelH + nfp * 16 * SROW + ko);
                bh[2 * nfp][0] = t4[0]; bh[2 * nfp][1] = t4[2];
                bh[2 * nfp + 1][0] = t4[1]; bh[2 * nfp + 1][1] = t4[3];
                ldsm4(t4, sb + bo + bRelL + nfp * 16 * SROW + ko);
                bl[2 * nfp][0] = t4[0]; bl[2 * nfp][1] = t4[2];
                bl[2 * nfp + 1][0] = t4[1]; bl[2 * nfp + 1][1] = t4[3];
            }
#pragma unroll
            for (int mf = 0; mf < 4; mf++) {
                u32 ah[4], al[4];
                ldsm4(ah, sb + bo + aRelH + mf * 16 * SROW + ko);
                ldsm4(al, sb + bo + aRelL + mf * 16 * SROW + ko);
#pragma unroll
                for (int nf = 0; nf < 4; nf++) {
                    mma_bf16(acc[mf][nf], ah, bh[nf][0], bh[nf][1]);
                    mma_bf16(acc[mf][nf], ah, bl[nf][0], bl[nf][1]);
                    mma_bf16(acc[mf][nf], al, bh[nf][0], bh[nf][1]);
                }
            }
        }

        if (c + 1 < NCHUNK) {
            STSALL(smem + ((c + 1) & 1) * (4 * STILE));
            __syncthreads();
        }
    }
#undef LOADC
#undef STSALL

#pragma unroll
    for (int mf = 0; mf < 4; mf++) {
        const int r0 = rowTile + wm * 64 + mf * 16 + (lane >> 2);
        const int r1 = r0 + 8;
#pragma unroll
        for (int nf = 0; nf < 4; nf++) {
            const int col = colTile + wn * 32 + nf * 8 + (lane & 3) * 2;
            float b0v = bias[col], b1v = bias[col + 1];
            if (r0 < Mrows)
                *(float2*)(Out + (long)r0 * Ncols + col) =
                    make_float2(acc[mf][nf][0] + b0v, acc[mf][nf][1] + b1v);
            if (r1 < Mrows)
                *(float2*)(Out + (long)r1 * Ncols + col) =
                    make_float2(acc[mf][nf][2] + b0v, acc[mf][nf][3] + b1v);
        }
    }
}

// ---------------- tensor-core attention (R12 proven) ----------------
#define SROWA  144
#define QPARTA (128 * SROWA)
#define KPARTA (M_PAD * SROWA)
#define ATT_SMEM (QPARTA + 3 * KPARTA + 256)

__global__ void __launch_bounds__(256, 2) attn_mma_kernel(
    const float* __restrict__ Q, const float* __restrict__ KV,
    __nv_bfloat16* __restrict__ Ch, __nv_bfloat16* __restrict__ Cl)
{
    extern __shared__ __align__(16) char smb[];
    char* sQ  = smb;
    char* sKh = smb + QPARTA;
    char* sKl = sKh + KPARTA;
    char* sV  = sKl + KPARTA;
    char* sKF = sV + KPARTA;

    const int b = blockIdx.z, h = blockIdx.y, qt = blockIdx.x;
    const int t = threadIdx.x, w = t >> 5, lane = t & 31;

    if (t < M_PAD) {
        int kf = -1;
        if (t >= 8) {
            int j = t - 8;
            kf = (j < 100) ? (j / 25) : (4 + (j - 100) / 24);
        }
        sKF[t] = (char)kf;
    }

    for (int s = t; s < M_PAD * 16; s += 256) {
        int m = s >> 4, c = s & 15;
        int mm = (m < M_G) ? m : (M_G - 1);
        long gk = (long)(b * M_G + mm) * (2 * CDIM) + h * HD + c * 4;
        float4 kv = *(const float4*)(KV + gk);
        u32 h0, l0, h1, l1;
        split2(kv.x, kv.y, h0, l0);
        split2(kv.z, kv.w, h1, l1);
        *(uint2*)(sKh + m * SROWA + c * 8) = make_uint2(h0, h1);
        *(uint2*)(sKl + m * SROWA + c * 8) = make_uint2(l0, l1);
        float4 vv = *(const float4*)(KV + gk + CDIM);
        *(uint2*)(sV + m * SROWA + c * 8) =
            make_uint2(h2pack(vv.x, vv.y), h2pack(vv.z, vv.w));
    }

    for (int s = t; s < 128 * 16; s += 256) {
        int r = s >> 4, c = s & 15;
        int qrow = qt * 128 + r; if (qrow >= NTOK) qrow = NTOK - 1;
        float4 v = *(const float4*)(Q + (long)(b * NTOK + qrow) * CDIM + h * HD + c * 4);
        u32 h0, l0, h1, l1;
        split2(v.x, v.y, h0, l0);
        split2(v.z, v.w, h1, l1);
        *(uint2*)(sQ + r * SROWA + c * 8) = make_uint2(h0, h1);
    }
    __syncthreads();

    u32 qh[4][4], ql[4][4];
    const u32 qa = smem_u32(sQ) + (w * 16 + (lane & 15)) * SROWA + (lane >> 4) * 16;
#pragma unroll
    for (int ks = 0; ks < 4; ks++) ldsm4(qh[ks], qa + ks * 32);
    __syncthreads();

    for (int s = t; s < 128 * 16; s += 256) {
        int r = s >> 4, c = s & 15;
        int qrow = qt * 128 + r; if (qrow >= NTOK) qrow = NTOK - 1;
        float4 v = *(const float4*)(Q + (long)(b * NTOK + qrow) * CDIM + h * HD + c * 4);
        u32 h0, l0, h1, l1;
        split2(v.x, v.y, h0, l0);
        split2(v.z, v.w, h1, l1);
        *(uint2*)(sQ + r * SROWA + c * 8) = make_uint2(l0, l1);
    }
    __syncthreads();
#pragma unroll
    for (int ks = 0; ks < 4; ks++) ldsm4(ql[ks], qa + ks * 32);

    const int q0 = qt * 128 + w * 16 + (lane >> 2);
    const int fr0 = q0 / N0;
    const int fr1 = (q0 + 8) / N0;

    float Oa[8][4];
#pragma unroll
    for (int i = 0; i < 8; i++)
#pragma unroll
        for (int j = 0; j < 4; j++) Oa[i][j] = 0.f;
    float rs0 = 0.f, rs1 = 0.f;

    const u32 kbH = smem_u32(sKh), kbL = smem_u32(sKl);
    const u32 vbF = smem_u32(sV);

    for (int kb = 0; kb < M_PAD / 32; kb++) {
        float S[4][4];
#pragma unroll
        for (int i = 0; i < 4; i++)
#pragma unroll
            for (int j = 0; j < 4; j++) S[i][j] = 0.f;

#pragma unroll
        for (int ks = 0; ks < 4; ks++) {
#pragma unroll
            for (int nfp = 0; nfp < 2; nfp++) {
                u32 off = (u32)(kb * 32 + nfp * 16 + (lane & 15)) * SROWA
                        + (lane >> 4) * 16 + ks * 32;
                u32 t4[4], s4[4];
                ldsm4(t4, kbH + off);
                ldsm4(s4, kbL + off);
                float* S0 = S[2 * nfp];
                float* S1 = S[2 * nfp + 1];
                mma_bf16(S0, qh[ks], t4[0], t4[2]);
                mma_bf16(S0, qh[ks], s4[0], s4[2]);
                mma_bf16(S0, ql[ks], t4[0], t4[2]);
                mma_bf16(S1, qh[ks], t4[1], t4[3]);
                mma_bf16(S1, qh[ks], s4[1], s4[3]);
                mma_bf16(S1, ql[ks], t4[1], t4[3]);
            }
        }

        u32 paF[2][4];
#pragma unroll
        for (int nf = 0; nf < 4; nf++) {
            int k0 = kb * 32 + nf * 8 + (lane & 3) * 2;
            int k1 = k0 + 1;
            int kf0 = sKF[k0], kf1 = sKF[k1];
            float c00 = (k0 < 8 || kf0 == fr0) ? 0.125f : 0.1f;
            float c01 = (k1 < 8 || kf1 == fr0) ? 0.125f : 0.1f;
            float c10 = (k0 < 8 || kf0 == fr1) ? 0.125f : 0.1f;
            float c11 = (k1 < 8 || kf1 == fr1) ? 0.125f : 0.1f;
            float p00 = (k0 < M_G) ? __expf(S[nf][0] * c00) : 0.f;
            float p01 = (k1 < M_G) ? __expf(S[nf][1] * c01) : 0.f;
            float p10 = (k0 < M_G) ? __expf(S[nf][2] * c10) : 0.f;
            float p11 = (k1 < M_G) ? __expf(S[nf][3] * c11) : 0.f;
            rs0 += p00 + p01;
            rs1 += p10 + p11;
            int j = nf >> 1, half = (nf & 1) << 1;
            paF[j][half]     = h2pack(p00, p01);
            paF[j][half + 1] = h2pack(p10, p11);
        }

#pragma unroll
        for (int j = 0; j < 2; j++) {
#pragma unroll
            for (int nd2 = 0; nd2 < 4; nd2++) {
                u32 v4[4];
                u32 off = (u32)(kb * 32 + j * 16 + (lane & 15)) * SROWA
                        + nd2 * 32 + (lane >> 4) * 16;
                ldsm4t(v4, vbF + off);
                mma_f16(Oa[2 * nd2],     paF[j], v4[0], v4[1]);
                mma_f16(Oa[2 * nd2 + 1], paF[j], v4[2], v4[3]);
            }
        }
    }

    rs0 += __shfl_xor_sync(0xFFFFFFFFu, rs0, 1);
    rs0 += __shfl_xor_sync(0xFFFFFFFFu, rs0, 2);
    rs1 += __shfl_xor_sync(0xFFFFFFFFu, rs1, 1);
    rs1 += __shfl_xor_sync(0xFFFFFFFFu, rs1, 2);
    const float inv0 = 1.f / rs0;
    const float inv1 = 1.f / rs1;

    const int n0 = q0;
    const int n1 = q0 + 8;
#pragma unroll
    for (int nd = 0; nd < 8; nd++) {
        int d = h * HD + nd * 8 + (lane & 3) * 2;
        if (n0 < NTOK) {
            u32 hh, ll;
            split2(Oa[nd][0] * inv0, Oa[nd][1] * inv0, hh, ll);
            long g = (long)(b * NTOK + n0) * CDIM + d;
            *(u32*)(Ch + g) = hh;
            *(u32*)(Cl + g) = ll;
        }
        if (n1 < NTOK) {
            u32 hh, ll;
            split2(Oa[nd][2] * inv1, Oa[nd][3] * inv1, hh, ll);
            long g = (long)(b * NTOK + n1) * CDIM + d;
            *(u32*)(Ch + g) = hh;
            *(u32*)(Cl + g) = ll;
        }
    }
}

// ---------------- launch ----------------
extern "C" void kernel_launch(void* const* d_in, const int* in_sizes, int n_in,
                              void* d_out, int out_size) {
    const float* x      = (const float*)d_in[0];
    const float* qkv_w  = (const float*)d_in[1];
    const float* proj_w = (const float*)d_in[2];
    const float* proj_b = (const float*)d_in[3];
    float* out          = (float*)d_out;

    float *Qp, *KVp;
    __nv_bfloat16 *Ph, *Pl, *Ch, *Cl;
    cudaGetSymbolAddress((void**)&Qp,  g_Q);
    cudaGetSymbolAddress((void**)&KVp, g_KV);
    cudaGetSymbolAddress((void**)&Ph,  g_Ph);
    cudaGetSymbolAddress((void**)&Pl,  g_Pl);
    cudaGetSymbolAddress((void**)&Ch,  g_Ch);
    cudaGetSymbolAddress((void**)&Cl,  g_Cl);

    cudaFuncSetAttribute(qkv_tf32_kernel,
                         cudaFuncAttributeMaxDynamicSharedMemorySize, QKV_SMEM);
    cudaFuncSetAttribute(proj_gemm_kernel,
                         cudaFuncAttributeMaxDynamicSharedMemorySize, GSMEM);
    cudaFuncSetAttribute(attn_mma_kernel,
                         cudaFuncAttributeMaxDynamicSharedMemorySize, ATT_SMEM);

    // ---- 0) split proj weights only ----
    {
        long np = (long)CDIM * KDIM;
        split_kernel<<<(int)((np / 4 + 255) / 256), 256>>>(proj_w, Ph, Pl, np);
    }
    // ---- 1) fused tf32 Q + KV GEMM ----
    qkv_tf32_kernel<<<QBLKS + 156, 256, QKV_SMEM>>>(
        x, qkv_w, qkv_w + (long)CDIM * KDIM, Qp, KVp);
    // ---- 2) tensor-core attention -> split bf16 ctx ----
    {
        dim3 grid((NTOK + 127) / 128, NHEAD, BATCH);
        attn_mma_kernel<<<grid, 256, ATT_SMEM>>>(Qp, KVp, Ch, Cl);
    }
    // ---- 3) out = ctx @ proj_w^T + proj_b ----
    proj_gemm_kernel<<<QBLKS, 256, GSMEM>>>(Ch, Cl, Ph, Pl, proj_b, out);
}

// round 15
// speedup vs baseline: 2.0282x; 1.0506x over previous
#include <cuda_runtime.h>
#include <cuda_bf16.h>
#include <cuda_fp16.h>
#include <math.h>
#include <stdint.h>

// ---------------- problem constants ----------------
#define B0      64
#define N0      197
#define CDIM    768
#define NHEAD   12
#define HD      64
#define FRAMES  8
#define BATCH   8
#define NTOK    1576
#define M_G     204
#define M_PAD   224
#define ROWS_TOT 12608
#define KDIM    768
#define KVROWS  (BATCH * M_G)       // 1632

typedef unsigned long long u64;
typedef unsigned int u32;

// ---------------- scratch ----------------
__device__ float g_Q[(long)ROWS_TOT * CDIM];
__device__ float g_KV[(long)KVROWS * 2 * CDIM];
__device__ float g_ctx[(long)ROWS_TOT * CDIM];

// ---------------- closed-form gather index ----------------
__device__ __forceinline__ int idx_token(int m) {
    if (m < 8) return m * N0;
    int j = m - 8;
    int i, t;
    if (j < 100) { i = j / 25; t = j - i * 25; }
    else         { int jj = j - 100; i = 4 + jj / 24; t = jj - (i - 4) * 24; }
    return i * (N0 + 1) + 1 + 8 * t;
}

// ---------------- helpers ----------------
__device__ __forceinline__ u32 smem_u32(const void* p) {
    u32 a;
    asm("{ .reg .u64 t; cvta.to.shared.u64 t, %1; cvt.u32.u64 %0, t; }"
        : "=r"(a) : "l"(p));
    return a;
}
__device__ __forceinline__ void ldsm4(u32* r, u32 addr) {
    asm volatile("ldmatrix.sync.aligned.m8n8.x4.shared.b16 {%0,%1,%2,%3}, [%4];"
        : "=r"(r[0]), "=r"(r[1]), "=r"(r[2]), "=r"(r[3]) : "r"(addr));
}
__device__ __forceinline__ void ldsm4t(u32* r, u32 addr) {
    asm volatile("ldmatrix.sync.aligned.m8n8.x4.trans.shared.b16 {%0,%1,%2,%3}, [%4];"
        : "=r"(r[0]), "=r"(r[1]), "=r"(r[2]), "=r"(r[3]) : "r"(addr));
}
__device__ __forceinline__ void mma_bf16(float* c, const u32* a, u32 b0, u32 b1) {
    asm volatile("mma.sync.aligned.m16n8k16.row.col.f32.bf16.bf16.f32 "
        "{%0,%1,%2,%3}, {%4,%5,%6,%7}, {%8,%9}, {%0,%1,%2,%3};"
        : "+f"(c[0]), "+f"(c[1]), "+f"(c[2]), "+f"(c[3])
        : "r"(a[0]), "r"(a[1]), "r"(a[2]), "r"(a[3]), "r"(b0), "r"(b1));
}
__device__ __forceinline__ void mma_f16(float* c, const u32* a, u32 b0, u32 b1) {
    asm volatile("mma.sync.aligned.m16n8k16.row.col.f32.f16.f16.f32 "
        "{%0,%1,%2,%3}, {%4,%5,%6,%7}, {%8,%9}, {%0,%1,%2,%3};"
        : "+f"(c[0]), "+f"(c[1]), "+f"(c[2]), "+f"(c[3])
        : "r"(a[0]), "r"(a[1]), "r"(a[2]), "r"(a[3]), "r"(b0), "r"(b1));
}
__device__ __forceinline__ void mma_tf32(float* c, float a0, float a1, float a2, float a3,
                                         float b0, float b1) {
    asm volatile("mma.sync.aligned.m16n8k8.row.col.f32.tf32.tf32.f32 "
        "{%0,%1,%2,%3}, {%4,%5,%6,%7}, {%8,%9}, {%0,%1,%2,%3};"
        : "+f"(c[0]), "+f"(c[1]), "+f"(c[2]), "+f"(c[3])
        : "r"(__float_as_uint(a0)), "r"(__float_as_uint(a1)),
          "r"(__float_as_uint(a2)), "r"(__float_as_uint(a3)),
          "r"(__float_as_uint(b0)), "r"(__float_as_uint(b1)));
}
__device__ __forceinline__ float cvt_tf32(float x) {
    u32 r;
    asm("cvt.rna.tf32.f32 %0, %1;" : "=r"(r) : "f"(x));
    return __uint_as_float(r);
}
__device__ __forceinline__ void split2(float x0, float x1, u32& hi, u32& lo) {
    __nv_bfloat162 h = __floats2bfloat162_rn(x0, x1);
    __nv_bfloat162 l = __floats2bfloat162_rn(x0 - __bfloat162float(h.x),
                                             x1 - __bfloat162float(h.y));
    hi = *reinterpret_cast<u32*>(&h);
    lo = *reinterpret_cast<u32*>(&l);
}
__device__ __forceinline__ u32 h2pack(float x0, float x1) {
    __half2 p = __floats2half2_rn(x0, x1);
    return *reinterpret_cast<u32*>(&p);
}

// ---------------- tf32 GEMM (tile 128x128, chunk 32, double-buffered) ----------------
// MODE 0: fused QKV  (750 blocks = 594 Q + 156 KV-gathered)
// MODE 1: proj + bias (594 blocks)
#define FROW 36                      // floats per smem row (144 B)
#define FTILE (128 * FROW)
#define TF32_SMEM (2 * 2 * FTILE * 4) // 73728 B
#define QBLKS 594

template<int MODE>
__global__ void __launch_bounds__(256, 2) tf32_gemm_kernel(
    const float* __restrict__ X, const float* __restrict__ W1,
    const float* __restrict__ W2, const float* __restrict__ bias,
    float* __restrict__ O1, float* __restrict__ O2)
{
    extern __shared__ __align__(16) float fs[];

    const int bid = blockIdx.x;
    int rowTile, colTile, Mrows, Ncols;
    bool gather = false;
    const float* W;
    float* Out;
    if (MODE == 0) {
        if (bid < QBLKS) {
            colTile = (bid % 6) * 128;  rowTile = (bid / 6) * 128;
            W = W1; Out = O1; Mrows = ROWS_TOT; Ncols = CDIM;
        } else {
            int id = bid - QBLKS;
            colTile = (id % 12) * 128;  rowTile = (id / 12) * 128;
            gather = true;
            W = W2; Out = O2; Mrows = KVROWS; Ncols = 2 * CDIM;
        }
    } else {
        colTile = (bid % 6) * 128;  rowTile = (bid / 6) * 128;
        W = W1; Out = O1; Mrows = ROWS_TOT; Ncols = CDIM;
    }

    const int t = threadIdx.x;
    const int wid = t >> 5, lane = t & 31;
    const int wm = wid >> 2, wn = wid & 3;

    const int lrow = t >> 1;          // 0..127
    const int half = t & 1;
    int arow = rowTile + lrow;
    if (arow >= Mrows) arow = Mrows - 1;
    if (gather) {
        int b = arow / M_G, m = arow - b * M_G;
        arow = b * NTOK + idx_token(m);
    }
    const long aIdx = (long)arow * KDIM + half * 16;
    const long bIdx = (long)(colTile + lrow) * KDIM + half * 16;
    const int stw = lrow * FROW + half * 16;

    float rA[16], rB[16];
#define LOADC(c) do {                                                  \
    long o = (long)(c) * 32;                                           \
    *(float4*)(rA + 0)  = *(const float4*)(X + aIdx + o);              \
    *(float4*)(rA + 4)  = *(const float4*)(X + aIdx + o + 4);          \
    *(float4*)(rA + 8)  = *(const float4*)(X + aIdx + o + 8);         \
    *(float4*)(rA + 12) = *(const float4*)(X + aIdx + o + 12);         \
    *(float4*)(rB + 0)  = *(const float4*)(W + bIdx + o);              \
    *(float4*)(rB + 4)  = *(const float4*)(W + bIdx + o + 4);          \
    *(float4*)(rB + 8)  = *(const float4*)(W + bIdx + o + 8);          \
    *(float4*)(rB + 12) = *(const float4*)(W + bIdx + o + 12);         \
} while (0)

#define STSALL(boff) do {                                              \
    float* _a = fs + (boff);                                           \
    float* _b = fs + (boff) + FTILE;                                   \
    _Pragma("unroll")                                                  \
    for (int i = 0; i < 16; i += 4) {                                  \
        float4 va = make_float4(cvt_tf32(rA[i]), cvt_tf32(rA[i+1]),    \
                                cvt_tf32(rA[i+2]), cvt_tf32(rA[i+3])); \
        float4 vb = make_float4(cvt_tf32(rB[i]), cvt_tf32(rB[i+1]),    \
                                cvt_tf32(rB[i+2]), cvt_tf32(rB[i+3])); \
        *(float4*)(_a + stw + i) = va;                                 \
        *(float4*)(_b + stw + i) = vb;                                 \
    }                                                                  \
} while (0)

    float acc[4][4][4];
#pragma unroll
    for (int i = 0; i < 4; i++)
#pragma unroll
        for (int j = 0; j < 4; j++)
#pragma unroll
            for (int q = 0; q < 4; q++) acc[i][j][q] = 0.f;

    LOADC(0);
    STSALL(0);
    __syncthreads();

    const int rA0 = wm * 64 + (lane >> 2);
    const int nB0 = wn * 32 + (lane >> 2);
    const int kc  = lane & 3;

    const int NCHUNK = KDIM / 32;   // 24
    for (int c = 0; c < NCHUNK; c++) {
        const int bo = (c & 1) * (2 * FTILE);
        if (c + 1 < NCHUNK) LOADC(c + 1);

        const float* As = fs + bo;
        const float* Bs = fs + bo + FTILE;

#pragma unroll
        for (int ks = 0; ks < 4; ks++) {
            const int k = ks * 8 + kc;
            float b0[4], b1[4];
#pragma unroll
            for (int nf = 0; nf < 4; nf++) {
                const float* br = Bs + (nB0 + nf * 8) * FROW;
                b0[nf] = br[k];
                b1[nf] = br[k + 4];
            }
#pragma unroll
            for (int mf = 0; mf < 4; mf++) {
                const float* ar0 = As + (rA0 + mf * 16) * FROW;
                const float* ar1 = ar0 + 8 * FROW;
                float a0 = ar0[k], a1 = ar1[k], a2 = ar0[k + 4], a3 = ar1[k + 4];
#pragma unroll
                for (int nf = 0; nf < 4; nf++)
                    mma_tf32(acc[mf][nf], a0, a1, a2, a3, b0[nf], b1[nf]);
            }
        }

        if (c + 1 < NCHUNK) {
            STSALL(((c + 1) & 1) * (2 * FTILE));
            __syncthreads();
        }
    }
#undef LOADC
#undef STSALL

#pragma unroll
    for (int mf = 0; mf < 4; mf++) {
        const int r0 = rowTile + wm * 64 + mf * 16 + (lane >> 2);
        const int r1 = r0 + 8;
#pragma unroll
        for (int nf = 0; nf < 4; nf++) {
            const int col = colTile + wn * 32 + nf * 8 + (lane & 3) * 2;
            float b0v = 0.f, b1v = 0.f;
            if (MODE == 1) { b0v = bias[col]; b1v = bias[col + 1]; }
            if (r0 < Mrows)
                *(float2*)(Out + (long)r0 * Ncols + col) =
                    make_float2(acc[mf][nf][0] + b0v, acc[mf][nf][1] + b1v);
            if (r1 < Mrows)
                *(float2*)(Out + (long)r1 * Ncols + col) =
                    make_float2(acc[mf][nf][2] + b0v, acc[mf][nf][3] + b1v);
        }
    }
}

// ---------------- tensor-core attention (fp32 ctx out) ----------------
#define SROWA  144
#define QPARTA (128 * SROWA)
#define KPARTA (M_PAD * SROWA)
#define ATT_SMEM (QPARTA + 3 * KPARTA + 256)

__global__ void __launch_bounds__(256, 2) attn_mma_kernel(
    const float* __restrict__ Q, const float* __restrict__ KV,
    float* __restrict__ Ctx)
{
    extern __shared__ __align__(16) char smb[];
    char* sQ  = smb;
    char* sKh = smb + QPARTA;
    char* sKl = sKh + KPARTA;
    char* sV  = sKl + KPARTA;
    char* sKF = sV + KPARTA;

    const int b = blockIdx.z, h = blockIdx.y, qt = blockIdx.x;
    const int t = threadIdx.x, w = t >> 5, lane = t & 31;

    if (t < M_PAD) {
        int kf = -1;
        if (t >= 8) {
            int j = t - 8;
            kf = (j < 100) ? (j / 25) : (4 + (j - 100) / 24);
        }
        sKF[t] = (char)kf;
    }

    for (int s = t; s < M_PAD * 16; s += 256) {
        int m = s >> 4, c = s & 15;
        int mm = (m < M_G) ? m : (M_G - 1);
        long gk = (long)(b * M_G + mm) * (2 * CDIM) + h * HD + c * 4;
        float4 kv = *(const float4*)(KV + gk);
        u32 h0, l0, h1, l1;
        split2(kv.x, kv.y, h0, l0);
        split2(kv.z, kv.w, h1, l1);
        *(uint2*)(sKh + m * SROWA + c * 8) = make_uint2(h0, h1);
        *(uint2*)(sKl + m * SROWA + c * 8) = make_uint2(l0, l1);
        float4 vv = *(const float4*)(KV + gk + CDIM);
        *(uint2*)(sV + m * SROWA + c * 8) =
            make_uint2(h2pack(vv.x, vv.y), h2pack(vv.z, vv.w));
    }

    for (int s = t; s < 128 * 16; s += 256) {
        int r = s >> 4, c = s & 15;
        int qrow = qt * 128 + r; if (qrow >= NTOK) qrow = NTOK - 1;
        float4 v = *(const float4*)(Q + (long)(b * NTOK + qrow) * CDIM + h * HD + c * 4);
        u32 h0, l0, h1, l1;
        split2(v.x, v.y, h0, l0);
        split2(v.z, v.w, h1, l1);
        *(uint2*)(sQ + r * SROWA + c * 8) = make_uint2(h0, h1);
    }
    __syncthreads();

    u32 qh[4][4], ql[4][4];
    const u32 qa = smem_u32(sQ) + (w * 16 + (lane & 15)) * SROWA + (lane >> 4) * 16;
#pragma unroll
    for (int ks = 0; ks < 4; ks++) ldsm4(qh[ks], qa + ks * 32);
    __syncthreads();

    for (int s = t; s < 128 * 16; s += 256) {
        int r = s >> 4, c = s & 15;
        int qrow = qt * 128 + r; if (qrow >= NTOK) qrow = NTOK - 1;
        float4 v = *(const float4*)(Q + (long)(b * NTOK + qrow) * CDIM + h * HD + c * 4);
        u32 h0, l0, h1, l1;
        split2(v.x, v.y, h0, l0);
        split2(v.z, v.w, h1, l1);
        *(uint2*)(sQ + r * SROWA + c * 8) = make_uint2(l0, l1);
    }
    __syncthreads();
#pragma unroll
    for (int ks = 0; ks < 4; ks++) ldsm4(ql[ks], qa + ks * 32);

    const int q0 = qt * 128 + w * 16 + (lane >> 2);
    const int fr0 = q0 / N0;
    const int fr1 = (q0 + 8) / N0;

    float Oa[8][4];
#pragma unroll
    for (int i = 0; i < 8; i++)
#pragma unroll
        for (int j = 0; j < 4; j++) Oa[i][j] = 0.f;
    float rs0 = 0.f, rs1 = 0.f;

    const u32 kbH = smem_u32(sKh), kbL = smem_u32(sKl);
    const u32 vbF = smem_u32(sV);

    for (int kb = 0; kb < M_PAD / 32; kb++) {
        float S[4][4];
#pragma unroll
        for (int i = 0; i < 4; i++)
#pragma unroll
            for (int j = 0; j < 4; j++) S[i][j] = 0.f;

#pragma unroll
        for (int ks = 0; ks < 4; ks++) {
#pragma unroll
            for (int nfp = 0; nfp < 2; nfp++) {
                u32 off = (u32)(kb * 32 + nfp * 16 + (lane & 15)) * SROWA
                        + (lane >> 4) * 16 + ks * 32;
                u32 t4[4], s4[4];
                ldsm4(t4, kbH + off);
                ldsm4(s4, kbL + off);
                float* S0 = S[2 * nfp];
                float* S1 = S[2 * nfp + 1];
                mma_bf16(S0, qh[ks], t4[0], t4[2]);
                mma_bf16(S0, qh[ks], s4[0], s4[2]);
                mma_bf16(S0, ql[ks], t4[0], t4[2]);
                mma_bf16(S1, qh[ks], t4[1], t4[3]);
                mma_bf16(S1, qh[ks], s4[1], s4[3]);
                mma_bf16(S1, ql[ks], t4[1], t4[3]);
            }
        }

        u32 paF[2][4];
#pragma unroll
        for (int nf = 0; nf < 4; nf++) {
            int k0 = kb * 32 + nf * 8 + (lane & 3) * 2;
            int k1 = k0 + 1;
            int kf0 = sKF[k0], kf1 = sKF[k1];
            float c00 = (k0 < 8 || kf0 == fr0) ? 0.125f : 0.1f;
            float c01 = (k1 < 8 || kf1 == fr0) ? 0.125f : 0.1f;
            float c10 = (k0 < 8 || kf0 == fr1) ? 0.125f : 0.1f;
            float c11 = (k1 < 8 || kf1 == fr1) ? 0.125f : 0.1f;
            float p00 = (k0 < M_G) ? __expf(S[nf][0] * c00) : 0.f;
            float p01 = (k1 < M_G) ? __expf(S[nf][1] * c01) : 0.f;
            float p10 = (k0 < M_G) ? __expf(S[nf][2] * c10) : 0.f;
            float p11 = (k1 < M_G) ? __expf(S[nf][3] * c11) : 0.f;
            rs0 += p00 + p01;
            rs1 += p10 + p11;
            int j = nf >> 1, half = (nf & 1) << 1;
            paF[j][half]     = h2pack(p00, p01);
            paF[j][half + 1] = h2pack(p10, p11);
        }

#pragma unroll
        for (int j = 0; j < 2; j++) {
#pragma unroll
            for (int nd2 = 0; nd2 < 4; nd2++) {
                u32 v4[4];
                u32 off = (u32)(kb * 32 + j * 16 + (lane & 15)) * SROWA
                        + nd2 * 32 + (lane >> 4) * 16;
                ldsm4t(v4, vbF + off);
                mma_f16(Oa[2 * nd2],     paF[j], v4[0], v4[1]);
                mma_f16(Oa[2 * nd2 + 1], paF[j], v4[2], v4[3]);
            }
        }
    }

    rs0 += __shfl_xor_sync(0xFFFFFFFFu, rs0, 1);
    rs0 += __shfl_xor_sync(0xFFFFFFFFu, rs0, 2);
    rs1 += __shfl_xor_sync(0xFFFFFFFFu, rs1, 1);
    rs1 += __shfl_xor_sync(0xFFFFFFFFu, rs1, 2);
    const float inv0 = 1.f / rs0;
    const float inv1 = 1.f / rs1;

    const int n0 = q0;
    const int n1 = q0 + 8;
#pragma unroll
    for (int nd = 0; nd < 8; nd++) {
        int d = h * HD + nd * 8 + (lane & 3) * 2;
        if (n0 < NTOK)
            *(float2*)(Ctx + (long)(b * NTOK + n0) * CDIM + d) =
                make_float2(Oa[nd][0] * inv0, Oa[nd][1] * inv0);
        if (n1 < NTOK)
            *(float2*)(Ctx + (long)(b * NTOK + n1) * CDIM + d) =
                make_float2(Oa[nd][2] * inv1, Oa[nd][3] * inv1);
    }
}

// ---------------- launch ----------------
extern "C" void kernel_launch(void* const* d_in, const int* in_sizes, int n_in,
                              void* d_out, int out_size) {
    const float* x      = (const float*)d_in[0];
    const float* qkv_w  = (const float*)d_in[1];
    const float* proj_w = (const float*)d_in[2];
    const float* proj_b = (const float*)d_in[3];
    float* out          = (float*)d_out;

    float *Qp, *KVp, *ctxp;
    cudaGetSymbolAddress((void**)&Qp,   g_Q);
    cudaGetSymbolAddress((void**)&KVp,  g_KV);
    cudaGetSymbolAddress((void**)&ctxp, g_ctx);

    cudaFuncSetAttribute(tf32_gemm_kernel<0>,
                         cudaFuncAttributeMaxDynamicSharedMemorySize, TF32_SMEM);
    cudaFuncSetAttribute(tf32_gemm_kernel<1>,
                         cudaFuncAttributeMaxDynamicSharedMemorySize, TF32_SMEM);
    cudaFuncSetAttribute(attn_mma_kernel,
                         cudaFuncAttributeMaxDynamicSharedMemorySize, ATT_SMEM);

    // ---- 1) fused tf32 Q + KV GEMM ----
    tf32_gemm_kernel<0><<<QBLKS + 156, 256, TF32_SMEM>>>(
        x, qkv_w, qkv_w + (long)CDIM * KDIM, nullptr, Qp, KVp);
    // ---- 2) tensor-core attention -> fp32 ctx ----
    {
        dim3 grid((NTOK + 127) / 128, NHEAD, BATCH);
        attn_mma_kernel<<<grid, 256, ATT_SMEM>>>(Qp, KVp, ctxp);
    }
    // ---- 3) out = ctx @ proj_w^T + proj_b (tf32) ----
    tf32_gemm_kernel<1><<<QBLKS, 256, TF32_SMEM>>>(
        ctxp, proj_w, nullptr, proj_b, out, nullptr);
}